// round 7
// baseline (speedup 1.0000x reference)
#include <cuda_runtime.h>
#include <cuda_bf16.h>
#include <cstdint>
#include <cstddef>

#define Bq   2
#define Sq   2048
#define HIDD 2048
#define NH   32
#define NKV  8
#define HD   64
#define QKVW ((NH + 2 * NKV) * HD)   /* 3072 */
#define GROUP (NH / NKV)             /* 4 */
#define SCALE 0.125f
#define LOG2E 1.4426950408889634f
#define QSCALE (SCALE * LOG2E)

#define MROWS   (Bq * Sq)            /* 4096 */
#define N_HID   (NH * HD)            /* 2048 */

// ---------------------------------------------------------------------------
// Scratch (device globals)
// ---------------------------------------------------------------------------
__device__ float g_qkv [(size_t)Bq * Sq * QKVW];
__device__ float g_attn[(size_t)MROWS * N_HID];

// int8 digit matrices + scales for the two projections
__device__ int8_t g_hidA1 [(size_t)MROWS * HIDD];
__device__ int8_t g_hidA2 [(size_t)MROWS * HIDD];
__device__ float  g_saHid [MROWS];
__device__ int8_t g_wqkvT1[(size_t)QKVW * HIDD];
__device__ int8_t g_wqkvT2[(size_t)QKVW * HIDD];
__device__ float  g_sbQkv [QKVW];
__device__ int8_t g_attA1 [(size_t)MROWS * N_HID];
__device__ int8_t g_attA2 [(size_t)MROWS * N_HID];
__device__ float  g_saAtt [MROWS];
__device__ int8_t g_woT1  [(size_t)HIDD * N_HID];
__device__ int8_t g_woT2  [(size_t)HIDD * N_HID];
__device__ float  g_sbWo  [HIDD];

// K bf16 hi/lo: [b, hk, kv, d]; V^T bf16 hi/lo: [b, hk, d, kv]
__device__ __nv_bfloat16 g_k_hi [(size_t)Bq * NKV * Sq * HD];
__device__ __nv_bfloat16 g_k_lo [(size_t)Bq * NKV * Sq * HD];
__device__ __nv_bfloat16 g_vt_hi[(size_t)Bq * NKV * HD * Sq];
__device__ __nv_bfloat16 g_vt_lo[(size_t)Bq * NKV * HD * Sq];

// ---------------------------------------------------------------------------
// Helpers
// ---------------------------------------------------------------------------
__device__ __forceinline__ uint32_t smem_u32(const void* p) {
    uint32_t a;
    asm("{ .reg .u64 t; cvta.to.shared.u64 t, %1; cvt.u32.u64 %0, t; }"
        : "=r"(a) : "l"(p));
    return a;
}
__device__ __forceinline__ uint32_t packbf(float x, float y) {   // lo=x, hi=y
    uint32_t r;
    asm("cvt.rn.bf16x2.f32 %0, %1, %2;" : "=r"(r) : "f"(y), "f"(x));
    return r;
}
__device__ __forceinline__ float2 unpackbf(uint32_t v) {
    __nv_bfloat162 t = *reinterpret_cast<__nv_bfloat162*>(&v);
    return make_float2(__bfloat162float(t.x), __bfloat162float(t.y));
}
__device__ __forceinline__ float ex2(float x) {
    float r; asm("ex2.approx.f32 %0, %1;" : "=f"(r) : "f"(x)); return r;
}

#define MMA_BF16(c, a, br0, br1) \
    asm volatile("mma.sync.aligned.m16n8k16.row.col.f32.bf16.bf16.f32 " \
        "{%0,%1,%2,%3}, {%4,%5,%6,%7}, {%8,%9}, {%0,%1,%2,%3};" \
        : "+f"((c)[0]), "+f"((c)[1]), "+f"((c)[2]), "+f"((c)[3]) \
        : "r"((a)[0]), "r"((a)[1]), "r"((a)[2]), "r"((a)[3]), "r"(br0), "r"(br1))

#define MMA_S8(c, a, b0v, b1v) \
    asm volatile("mma.sync.aligned.m16n8k32.row.col.s32.s8.s8.s32 " \
        "{%0,%1,%2,%3}, {%4,%5,%6,%7}, {%8,%9}, {%0,%1,%2,%3};" \
        : "+r"((c)[0]), "+r"((c)[1]), "+r"((c)[2]), "+r"((c)[3]) \
        : "r"((a)[0]), "r"((a)[1]), "r"((a)[2]), "r"((a)[3]), "r"(b0v), "r"(b1v))

#define LDMATRIX_X4(r, addr) \
    asm volatile("ldmatrix.sync.aligned.m8n8.x4.shared.b16 {%0,%1,%2,%3}, [%4];" \
        : "=r"((r)[0]), "=r"((r)[1]), "=r"((r)[2]), "=r"((r)[3]) : "r"(addr))

#define CP_ASYNC16(saddr, gptr) \
    asm volatile("cp.async.cg.shared.global [%0], [%1], 16;" :: "r"(saddr), "l"(gptr))
#define CP_COMMIT() asm volatile("cp.async.commit_group;" ::: "memory")
template <int N> __device__ __forceinline__ void cp_wait() {
    asm volatile("cp.async.wait_group %0;" :: "n"(N) : "memory");
}

// ---------------------------------------------------------------------------
// Row-wise two-digit int8 quantization: X[R x C] -> D1, D2, S (sa = rowmax/127)
// One block per row, 256 threads, C = 2048.
// ---------------------------------------------------------------------------
__global__ __launch_bounds__(256) void quant_rows(
    const float* __restrict__ X, int8_t* __restrict__ D1, int8_t* __restrict__ D2,
    float* __restrict__ S, int C)
{
    const int row = blockIdx.x;
    const int tid = threadIdx.x;
    const float* xr = X + (size_t)row * C + tid * 8;
    float v[8];
    *(float4*)(v)     = *(const float4*)(xr);
    *(float4*)(v + 4) = *(const float4*)(xr + 4);

    float mx = 0.f;
    #pragma unroll
    for (int j = 0; j < 8; j++) mx = fmaxf(mx, fabsf(v[j]));

    __shared__ float red[256];
    red[tid] = mx;
    __syncthreads();
    #pragma unroll
    for (int ofs = 128; ofs > 0; ofs >>= 1) {
        if (tid < ofs) red[tid] = fmaxf(red[tid], red[tid + ofs]);
        __syncthreads();
    }
    float s  = fmaxf(red[0], 1e-30f);
    float sa = s * (1.0f / 127.0f);
    float inv = 127.0f / s;

    uint32_t p1[2] = {0, 0}, p2[2] = {0, 0};
    #pragma unroll
    for (int j = 0; j < 8; j++) {
        int d1 = __float2int_rn(v[j] * inv);
        float r = v[j] - (float)d1 * sa;
        int d2 = __float2int_rn(r * inv * 127.0f);
        p1[j >> 2] |= ((uint32_t)(d1 & 255)) << ((j & 3) * 8);
        p2[j >> 2] |= ((uint32_t)(d2 & 255)) << ((j & 3) * 8);
    }
    size_t o = (size_t)row * C + tid * 8;
    *(uint2*)(D1 + o) = make_uint2(p1[0], p1[1]);
    *(uint2*)(D2 + o) = make_uint2(p2[0], p2[1]);
    if (tid == 0) S[row] = sa;
}

// ---------------------------------------------------------------------------
// Column max of W[R x C] -> S[c] = colmax/127
// ---------------------------------------------------------------------------
__global__ __launch_bounds__(256) void colmax_kernel(
    const float* __restrict__ W, float* __restrict__ S, int R, int C)
{
    int c = blockIdx.x * 256 + threadIdx.x;
    float mx = 0.f;
    for (int r = 0; r < R; r++) mx = fmaxf(mx, fabsf(W[(size_t)r * C + c]));
    S[c] = fmaxf(mx, 1e-30f) * (1.0f / 127.0f);
}

// ---------------------------------------------------------------------------
// Transpose + two-digit quantize: W[R x C] fp32 -> T1,T2 int8 [C x R]
// S[c] precomputed by colmax_kernel.
// ---------------------------------------------------------------------------
__global__ void transpose_quant(const float* __restrict__ B, const float* __restrict__ S,
                                int8_t* __restrict__ T1, int8_t* __restrict__ T2,
                                int R, int C)
{
    __shared__ float t[32][33];
    int x = blockIdx.x * 32 + threadIdx.x;
    int y = blockIdx.y * 32 + threadIdx.y;
    #pragma unroll
    for (int j = 0; j < 32; j += 8)
        t[threadIdx.y + j][threadIdx.x] = B[(size_t)(y + j) * C + x];
    __syncthreads();
    int ox = blockIdx.y * 32 + threadIdx.x;  // col in T (row in B)
    int oy = blockIdx.x * 32 + threadIdx.y;  // row in T (col in B)
    #pragma unroll
    for (int j = 0; j < 32; j += 8) {
        float v = t[threadIdx.x][threadIdx.y + j];
        float sb = S[oy + j];
        float inv = 1.0f / sb;
        int d1 = __float2int_rn(v * inv);
        float r = v - (float)d1 * sb;
        int d2 = __float2int_rn(r * inv * 127.0f);
        size_t o = (size_t)(oy + j) * R + ox;
        T1[o] = (int8_t)d1;
        T2[o] = (int8_t)d2;
    }
}

// ---------------------------------------------------------------------------
// int8 digit GEMM: C[M,N] = (SA.*A) * (SB.*B)^T with A,B two-digit int8.
// CTA 128x128, 8 warps (warp 32x64), K-chunk 64, 2-stage cp.async pipeline.
// P1 = d1*e1, P2 = d1*e2 + d2*e1 (exact int32); C = sa*sb*(P1 + P2/127).
// ---------------------------------------------------------------------------
#define ROWB       80            /* 64B data + 16B pad */
#define TILEB      (128 * ROWB)  /* 10240 */
#define STAGEB     (4 * TILEB)   /* 40960: A1, A2, B1, B2 */
#define GEMM_SMEM  (2 * STAGEB)  /* 81920 */

__global__ __launch_bounds__(256, 1) void gemm_imma(
    int M, int N, int K,
    const int8_t* __restrict__ A1, const int8_t* __restrict__ A2,
    const float* __restrict__ SA,
    const int8_t* __restrict__ B1, const int8_t* __restrict__ B2,
    const float* __restrict__ SB,
    float* __restrict__ C)
{
    extern __shared__ char smem[];
    const uint32_t sbase = smem_u32(smem);
    const int tid  = threadIdx.x;
    const int wid  = tid >> 5;
    const int lane = tid & 31;
    const int m0 = blockIdx.y * 128;
    const int n0 = blockIdx.x * 128;
    const int wm = (wid >> 1) * 32;
    const int wn = (wid & 1) * 64;

    const int8_t* srcs[4] = {
        A1 + (size_t)m0 * K, A2 + (size_t)m0 * K,
        B1 + (size_t)n0 * K, B2 + (size_t)n0 * K
    };

    const int q  = lane >> 3;
    const int ri = lane & 7;
    const int a_row_add = ((q & 1) << 3) + ri;
    const int a_col_add = (q >> 1) << 4;       // 16-byte chunks
    const int b_row_add = ((q >> 1) << 3) + ri;
    const int b_col_add = (q & 1) << 4;

    int p1[2][8][4], p2[2][8][4];
    #pragma unroll
    for (int mi = 0; mi < 2; mi++)
        #pragma unroll
        for (int ni = 0; ni < 8; ni++)
            #pragma unroll
            for (int c = 0; c < 4; c++) { p1[mi][ni][c] = 0; p2[mi][ni][c] = 0; }

    const int NC = K >> 6;   // chunks of 64

    auto load_chunk = [&](int stage, int k0) {
        uint32_t sdst = sbase + stage * STAGEB;
        #pragma unroll
        for (int t = 0; t < 4; t++) {
            #pragma unroll
            for (int u = 0; u < 2; u++) {
                int idx = tid + u * 256;        // 0..511
                int row = idx >> 2;
                int seg = idx & 3;
                const int8_t* g = srcs[t] + (size_t)row * K + k0 + seg * 16;
                CP_ASYNC16(sdst + t * TILEB + row * ROWB + seg * 16, g);
            }
        }
        CP_COMMIT();
    };

    load_chunk(0, 0);

    for (int i = 0; i < NC; i++) {
        const int s = i & 1;
        if (i + 1 < NC) { load_chunk(s ^ 1, (i + 1) << 6); cp_wait<1>(); }
        else           { cp_wait<0>(); }
        __syncthreads();

        const uint32_t st = sbase + s * STAGEB;
        #pragma unroll
        for (int kk = 0; kk < 64; kk += 32) {
            uint32_t a1f[2][4], a2f[2][4];
            #pragma unroll
            for (int mi = 0; mi < 2; mi++) {
                int row = wm + mi * 16 + a_row_add;
                uint32_t cb = kk + a_col_add;
                LDMATRIX_X4(a1f[mi], st + 0 * TILEB + row * ROWB + cb);
                LDMATRIX_X4(a2f[mi], st + 1 * TILEB + row * ROWB + cb);
            }
            #pragma unroll
            for (int nj = 0; nj < 4; nj++) {
                uint32_t b1f[4], b2f[4];
                int row = wn + nj * 16 + b_row_add;
                uint32_t cb = kk + b_col_add;
                LDMATRIX_X4(b1f, st + 2 * TILEB + row * ROWB + cb);
                LDMATRIX_X4(b2f, st + 3 * TILEB + row * ROWB + cb);
                #pragma unroll
                for (int mi = 0; mi < 2; mi++) {
                    #pragma unroll
                    for (int hh = 0; hh < 2; hh++) {
                        int ni = nj * 2 + hh;
                        MMA_S8(p1[mi][ni], a1f[mi], b1f[hh*2], b1f[hh*2+1]);
                        MMA_S8(p2[mi][ni], a1f[mi], b2f[hh*2], b2f[hh*2+1]);
                        MMA_S8(p2[mi][ni], a2f[mi], b1f[hh*2], b1f[hh*2+1]);
                    }
                }
            }
        }
        __syncthreads();
    }

    const int g  = lane >> 2;
    const int tg = lane & 3;
    const float inv127 = 1.0f / 127.0f;
    #pragma unroll
    for (int mi = 0; mi < 2; mi++) {
        int row = m0 + wm + mi * 16 + g;
        float sar0 = SA[row], sar1 = SA[row + 8];
        #pragma unroll
        for (int ni = 0; ni < 8; ni++) {
            int col = n0 + wn + ni * 8 + tg * 2;
            float sb0 = SB[col], sb1 = SB[col + 1];
            float c00 = sar0 * sb0 * ((float)p1[mi][ni][0] + (float)p2[mi][ni][0] * inv127);
            float c01 = sar0 * sb1 * ((float)p1[mi][ni][1] + (float)p2[mi][ni][1] * inv127);
            float c10 = sar1 * sb0 * ((float)p1[mi][ni][2] + (float)p2[mi][ni][2] * inv127);
            float c11 = sar1 * sb1 * ((float)p1[mi][ni][3] + (float)p2[mi][ni][3] * inv127);
            *(float2*)(C + (size_t)row * N + col)       = make_float2(c00, c01);
            *(float2*)(C + (size_t)(row + 8) * N + col) = make_float2(c10, c11);
        }
    }
}

// ---------------------------------------------------------------------------
// RoPE
// ---------------------------------------------------------------------------
__global__ void rope_kernel(const int* __restrict__ positions)
{
    const int total = Bq * Sq * (NH + NKV) * (HD / 2);
    int idx = blockIdx.x * blockDim.x + threadIdx.x;
    if (idx >= total) return;

    int i  = idx & (HD / 2 - 1);
    int hh = (idx >> 5) % (NH + NKV);
    int bs = idx / ((HD / 2) * (NH + NKV));

    float pos = (float)positions[bs];
    float inv = __expf(-((float)(2 * i) / (float)HD) * 9.210340371976184f);
    float f = pos * inv;
    float c = cosf(f), s = sinf(f);

    float* p = g_qkv + (size_t)bs * QKVW + hh * HD;
    float x1 = p[i];
    float x2 = p[i + HD / 2];
    p[i]          = x1 * c - x2 * s;
    p[i + HD / 2] = x2 * c + x1 * s;
}

// ---------------------------------------------------------------------------
// K/V global bf16 hi/lo conversion; V transposed. grid (32, NKV, Bq), 256 thr
// ---------------------------------------------------------------------------
__global__ __launch_bounds__(256) void convert_kv()
{
    int jt = blockIdx.x, hk = blockIdx.y, b = blockIdx.z;
    int tid = threadIdx.x;
    __shared__ float vt[64][65];

    int r    = tid >> 2;
    int dseg = (tid & 3) * 16;

    const float* ksrc = g_qkv + (size_t)(b * Sq + jt * 64 + r) * QKVW + NH * HD + hk * HD;
    const float* vsrc = g_qkv + (size_t)(b * Sq + jt * 64 + r) * QKVW + (NH + NKV) * HD + hk * HD;
    __nv_bfloat16* khid = g_k_hi + ((size_t)(b * NKV + hk) * Sq + jt * 64 + r) * HD;
    __nv_bfloat16* klod = g_k_lo + ((size_t)(b * NKV + hk) * Sq + jt * 64 + r) * HD;

    #pragma unroll
    for (int i = 0; i < 4; i++) {
        int d = dseg + i * 4;
        float4 f = *(const float4*)(ksrc + d);
        uint32_t h01 = packbf(f.x, f.y), h23 = packbf(f.z, f.w);
        float2 u01 = unpackbf(h01), u23 = unpackbf(h23);
        uint32_t l01 = packbf(f.x - u01.x, f.y - u01.y);
        uint32_t l23 = packbf(f.z - u23.x, f.w - u23.y);
        *(uint2*)(khid + d) = make_uint2(h01, h23);
        *(uint2*)(klod + d) = make_uint2(l01, l23);

        float4 v = *(const float4*)(vsrc + d);
        vt[r][d + 0] = v.x; vt[r][d + 1] = v.y; vt[r][d + 2] = v.z; vt[r][d + 3] = v.w;
    }
    __syncthreads();

    int d = tid >> 2;
    int kseg = (tid & 3) * 16;
    uint32_t hi8[8], lo8[8];
    #pragma unroll
    for (int i = 0; i < 8; i++) {
        float a = vt[kseg + 2 * i][d];
        float c = vt[kseg + 2 * i + 1][d];
        uint32_t h = packbf(a, c);
        float2 u = unpackbf(h);
        hi8[i] = h;
        lo8[i] = packbf(a - u.x, c - u.y);
    }
    size_t vo = ((size_t)(b * NKV + hk) * HD + d) * Sq + jt * 64 + kseg;
    *(uint4*)(g_vt_hi + vo)     = make_uint4(hi8[0], hi8[1], hi8[2], hi8[3]);
    *(uint4*)(g_vt_hi + vo + 8) = make_uint4(hi8[4], hi8[5], hi8[6], hi8[7]);
    *(uint4*)(g_vt_lo + vo)     = make_uint4(lo8[0], lo8[1], lo8[2], lo8[3]);
    *(uint4*)(g_vt_lo + vo + 8) = make_uint4(lo8[4], lo8[5], lo8[6], lo8[7]);
}

// ---------------------------------------------------------------------------
// mma.sync flash attention (R5-proven). grid (16, NH, Bq), 256 threads.
// q-tile 128, kv-chunk 128 per stage. Epilogue writes fp32 g_attn.
// ---------------------------------------------------------------------------
#define ATT_KROWB  144
#define ATT_KTILE  (128 * ATT_KROWB)
#define ATT_VROWB  272
#define ATT_VTILE  (64 * ATT_VROWB)
#define ATT_VOFF   (2 * ATT_KTILE)
#define ATT_STAGEB (ATT_VOFF + 2 * ATT_VTILE)
#define ATT_SMEM   (2 * ATT_STAGEB)

__global__ __launch_bounds__(256, 1) void attn_mma()
{
    const int qt = (int)gridDim.x - 1 - (int)blockIdx.x;
    const int h  = blockIdx.y;
    const int b  = blockIdx.z;
    const int hk = h / GROUP;
    const int q0 = qt * 128;

    extern __shared__ char smem[];
    const uint32_t sb = smem_u32(smem);
    const int tid  = threadIdx.x;
    const int wid  = tid >> 5;
    const int lane = tid & 31;
    const int wm   = wid * 16;
    const int g  = lane >> 2;
    const int tg = lane & 3;
    const int q  = lane >> 3;
    const int ri = lane & 7;
    const int b_row_add = ((q >> 1) << 3) + ri;
    const int b_col_add = (q & 1) << 3;

    uint32_t qa_hi[4][4], qa_lo[4][4];
    {
        const float* qbase = g_qkv + (size_t)(b * Sq + q0 + wm) * QKVW + h * HD;
        #pragma unroll
        for (int kb = 0; kb < 4; kb++) {
            #pragma unroll
            for (int p = 0; p < 4; p++) {
                int row = g + (p & 1) * 8;
                int col = kb * 16 + tg * 2 + (p >> 1) * 8;
                float2 f = *(const float2*)(qbase + (size_t)row * QKVW + col);
                f.x *= QSCALE; f.y *= QSCALE;
                uint32_t hh = packbf(f.x, f.y);
                float2 u = unpackbf(hh);
                qa_hi[kb][p] = hh;
                qa_lo[kb][p] = packbf(f.x - u.x, f.y - u.y);
            }
        }
    }

    float oacc[8][4];
    #pragma unroll
    for (int n = 0; n < 8; n++)
        #pragma unroll
        for (int j = 0; j < 4; j++) oacc[n][j] = 0.f;
    float m0 = -1e30f, m1 = -1e30f, l0 = 0.f, l1 = 0.f;

    const __nv_bfloat16* khi = g_k_hi  + (size_t)(b * NKV + hk) * Sq * HD;
    const __nv_bfloat16* klo = g_k_lo  + (size_t)(b * NKV + hk) * Sq * HD;
    const __nv_bfloat16* vhi = g_vt_hi + (size_t)(b * NKV + hk) * HD * Sq;
    const __nv_bfloat16* vlo = g_vt_lo + (size_t)(b * NKV + hk) * HD * Sq;

    const int nchunks = qt + 1;

    auto load = [&](int stg, int ct) {
        uint32_t dst = sb + stg * ATT_STAGEB;
        int j0 = ct * 128;
        #pragma unroll
        for (int k = 0; k < 16; k++) {
            int c = tid + k * 256;
            int t = c >> 10;
            if (t < 2) {
                int row = (c >> 3) & 127;
                int seg = c & 7;
                const __nv_bfloat16* src = (t == 0 ? khi : klo) + (size_t)(j0 + row) * HD + seg * 8;
                CP_ASYNC16(dst + t * ATT_KTILE + row * ATT_KROWB + seg * 16, src);
            } else {
                int row = (c >> 4) & 63;
                int seg = c & 15;
                const __nv_bfloat16* src = (t == 2 ? vhi : vlo) + (size_t)row * Sq + j0 + seg * 8;
                CP_ASYNC16(dst + ATT_VOFF + (t - 2) * ATT_VTILE + row * ATT_VROWB + seg * 16, src);
            }
        }
        CP_COMMIT();
    };

    load(0, 0);

    for (int t = 0; t < nchunks; t++) {
        const int s = t & 1;
        if (t + 1 < nchunks) { load(s ^ 1, t + 1); cp_wait<1>(); }
        else                 { cp_wait<0>(); }
        __syncthreads();

        const uint32_t st = sb + s * ATT_STAGEB;
        #pragma unroll
        for (int half = 0; half < 2; half++) {
            const int j0 = t * 128 + half * 64;
            if (j0 <= q0 + wm + 15) {
                float sc[8][4];
                #pragma unroll
                for (int n = 0; n < 8; n++)
                    #pragma unroll
                    for (int j = 0; j < 4; j++) sc[n][j] = 0.f;

                #pragma unroll
                for (int kb = 0; kb < 4; kb++) {
                    #pragma unroll
                    for (int nj = 0; nj < 4; nj++) {
                        uint32_t bh[4], bl[4];
                        uint32_t addr = st + (half * 64 + nj * 16 + b_row_add) * ATT_KROWB
                                        + (kb * 16 + b_col_add) * 2;
                        LDMATRIX_X4(bh, addr);
                        LDMATRIX_X4(bl, addr + ATT_KTILE);
                        #pragma unroll
                        for (int hh = 0; hh < 2; hh++) {
                            int n = nj * 2 + hh;
                            MMA_BF16(sc[n], qa_hi[kb], bh[hh*2], bh[hh*2+1]);
                            MMA_BF16(sc[n], qa_hi[kb], bl[hh*2], bl[hh*2+1]);
                            MMA_BF16(sc[n], qa_lo[kb], bh[hh*2], bh[hh*2+1]);
                        }
                    }
                }

                if (j0 + 63 > q0 + wm) {
                    int r0 = q0 + wm + g;
                    #pragma unroll
                    for (int n = 0; n < 8; n++) {
                        int cb = j0 + n * 8 + tg * 2;
                        if (cb     > r0)     sc[n][0] = -1e30f;
                        if (cb + 1 > r0)     sc[n][1] = -1e30f;
                        if (cb     > r0 + 8) sc[n][2] = -1e30f;
                        if (cb + 1 > r0 + 8) sc[n][3] = -1e30f;
                    }
                }

                float mx0 = -1e30f, mx1 = -1e30f;
                #pragma unroll
                for (int n = 0; n < 8; n++) {
                    mx0 = fmaxf(mx0, fmaxf(sc[n][0], sc[n][1]));
                    mx1 = fmaxf(mx1, fmaxf(sc[n][2], sc[n][3]));
                }
                mx0 = fmaxf(mx0, __shfl_xor_sync(0xffffffffu, mx0, 1));
                mx0 = fmaxf(mx0, __shfl_xor_sync(0xffffffffu, mx0, 2));
                mx1 = fmaxf(mx1, __shfl_xor_sync(0xffffffffu, mx1, 1));
                mx1 = fmaxf(mx1, __shfl_xor_sync(0xffffffffu, mx1, 2));

                float nm0 = fmaxf(m0, mx0), nm1 = fmaxf(m1, mx1);
                float corr0 = ex2(m0 - nm0), corr1 = ex2(m1 - nm1);
                m0 = nm0; m1 = nm1;

                float s0 = 0.f, s1 = 0.f;
                #pragma unroll
                for (int n = 0; n < 8; n++) {
                    sc[n][0] = ex2(sc[n][0] - nm0);
                    sc[n][1] = ex2(sc[n][1] - nm0);
                    sc[n][2] = ex2(sc[n][2] - nm1);
                    sc[n][3] = ex2(sc[n][3] - nm1);
                    s0 += sc[n][0] + sc[n][1];
                    s1 += sc[n][2] + sc[n][3];
                }
                s0 += __shfl_xor_sync(0xffffffffu, s0, 1);
                s0 += __shfl_xor_sync(0xffffffffu, s0, 2);
                s1 += __shfl_xor_sync(0xffffffffu, s1, 1);
                s1 += __shfl_xor_sync(0xffffffffu, s1, 2);
                l0 = l0 * corr0 + s0;
                l1 = l1 * corr1 + s1;

                #pragma unroll
                for (int n = 0; n < 8; n++) {
                    oacc[n][0] *= corr0; oacc[n][1] *= corr0;
                    oacc[n][2] *= corr1; oacc[n][3] *= corr1;
                }

                uint32_t pa_hi[4][4], pa_lo[4][4];
                #pragma unroll
                for (int kb = 0; kb < 4; kb++) {
                    #pragma unroll
                    for (int hh = 0; hh < 2; hh++) {
                        int n = 2 * kb + hh;
                        uint32_t h0 = packbf(sc[n][0], sc[n][1]);
                        uint32_t h1 = packbf(sc[n][2], sc[n][3]);
                        float2 u0 = unpackbf(h0), u1 = unpackbf(h1);
                        pa_hi[kb][hh * 2 + 0] = h0;
                        pa_hi[kb][hh * 2 + 1] = h1;
                        pa_lo[kb][hh * 2 + 0] = packbf(sc[n][0] - u0.x, sc[n][1] - u0.y);
                        pa_lo[kb][hh * 2 + 1] = packbf(sc[n][2] - u1.x, sc[n][3] - u1.y);
                    }
                }

                #pragma unroll
                for (int kb = 0; kb < 4; kb++) {
                    #pragma unroll
                    for (int dg = 0; dg < 4; dg++) {
                        uint32_t vh[4], vl[4];
                        uint32_t addr = st + ATT_VOFF + (dg * 16 + b_row_add) * ATT_VROWB
                                        + (half * 64 + kb * 16 + b_col_add) * 2;
                        LDMATRIX_X4(vh, addr);
                        LDMATRIX_X4(vl, addr + ATT_VTILE);
                        #pragma unroll
                        for (int hh = 0; hh < 2; hh++) {
                            int n = dg * 2 + hh;
                            MMA_BF16(oacc[n], pa_hi[kb], vh[hh*2], vh[hh*2+1]);
                            MMA_BF16(oacc[n], pa_hi[kb], vl[hh*2], vl[hh*2+1]);
                            MMA_BF16(oacc[n], pa_lo[kb], vh[hh*2], vh[hh*2+1]);
                        }
                    }
                }
            }
        }
        __syncthreads();
    }

    float inv0 = 1.f / l0, inv1 = 1.f / l1;
    int row0 = q0 + wm + g;
    #pragma unroll
    for (int n = 0; n < 8; n++) {
        int col = h * HD + n * 8 + tg * 2;
        size_t o0 = (size_t)(b * Sq + row0) * N_HID + col;
        size_t o1 = (size_t)(b * Sq + row0 + 8) * N_HID + col;
        *(float2*)(g_attn + o0) = make_float2(oacc[n][0] * inv0, oacc[n][1] * inv0);
        *(float2*)(g_attn + o1) = make_float2(oacc[n][2] * inv1, oacc[n][3] * inv1);
    }
}

// ---------------------------------------------------------------------------
// Launch pipeline
// ---------------------------------------------------------------------------
extern "C" void kernel_launch(void* const* d_in, const int* in_sizes, int n_in,
                              void* d_out, int out_size)
{
    const int*   positions = (const int*)d_in[0];
    const float* hidden    = (const float*)d_in[1];
    const float* Wqkv      = (const float*)d_in[2];
    const float* Wo        = (const float*)d_in[3];
    float*       out       = (float*)d_out;

    float *qkv, *attn;
    cudaGetSymbolAddress((void**)&qkv,  g_qkv);
    cudaGetSymbolAddress((void**)&attn, g_attn);
    int8_t *hidA1, *hidA2, *wqkvT1, *wqkvT2, *attA1, *attA2, *woT1, *woT2;
    float  *saHid, *sbQkv, *saAtt, *sbWo;
    cudaGetSymbolAddress((void**)&hidA1,  g_hidA1);
    cudaGetSymbolAddress((void**)&hidA2,  g_hidA2);
    cudaGetSymbolAddress((void**)&saHid,  g_saHid);
    cudaGetSymbolAddress((void**)&wqkvT1, g_wqkvT1);
    cudaGetSymbolAddress((void**)&wqkvT2, g_wqkvT2);
    cudaGetSymbolAddress((void**)&sbQkv,  g_sbQkv);
    cudaGetSymbolAddress((void**)&attA1,  g_attA1);
    cudaGetSymbolAddress((void**)&attA2,  g_attA2);
    cudaGetSymbolAddress((void**)&saAtt,  g_saAtt);
    cudaGetSymbolAddress((void**)&woT1,   g_woT1);
    cudaGetSymbolAddress((void**)&woT2,   g_woT2);
    cudaGetSymbolAddress((void**)&sbWo,   g_sbWo);

    cudaFuncSetAttribute(gemm_imma, cudaFuncAttributeMaxDynamicSharedMemorySize, GEMM_SMEM);
    cudaFuncSetAttribute(attn_mma,  cudaFuncAttributeMaxDynamicSharedMemorySize, ATT_SMEM);

    // hidden -> int8 digits + row scales
    quant_rows<<<MROWS, 256>>>(hidden, hidA1, hidA2, saHid, HIDD);
    // Wqkv -> col scales, transposed digits
    colmax_kernel<<<QKVW / 256, 256>>>(Wqkv, sbQkv, HIDD, QKVW);
    transpose_quant<<<dim3(QKVW / 32, HIDD / 32), dim3(32, 8)>>>(Wqkv, sbQkv, wqkvT1, wqkvT2, HIDD, QKVW);

    // QKV projection (int8 IMMA)
    gemm_imma<<<dim3(QKVW / 128, MROWS / 128), 256, GEMM_SMEM>>>(
        MROWS, QKVW, HIDD, hidA1, hidA2, saHid, wqkvT1, wqkvT2, sbQkv, qkv);

    // RoPE (q + k)
    {
        int total = Bq * Sq * (NH + NKV) * (HD / 2);
        rope_kernel<<<(total + 255) / 256, 256>>>(positions);
    }

    // K/V -> bf16 hi/lo (V transposed)
    convert_kv<<<dim3(Sq / 64, NKV, Bq), 256>>>();

    // Flash attention (writes fp32 g_attn)
    attn_mma<<<dim3(Sq / 128, NH, Bq), 256, ATT_SMEM>>>();

    // attention out -> int8 digits + row scales
    quant_rows<<<MROWS, 256>>>(attn, attA1, attA2, saAtt, N_HID);
    // Wo -> col scales, transposed digits
    colmax_kernel<<<HIDD / 256, 256>>>(Wo, sbWo, N_HID, HIDD);
    transpose_quant<<<dim3(HIDD / 32, N_HID / 32), dim3(32, 8)>>>(Wo, sbWo, woT1, woT2, N_HID, HIDD);

    // Output projection (int8 IMMA)
    gemm_imma<<<dim3(HIDD / 128, MROWS / 128), 256, GEMM_SMEM>>>(
        MROWS, HIDD, N_HID, attA1, attA2, saAtt, woT1, woT2, sbWo, out);
}

// round 8
// speedup vs baseline: 3.0315x; 3.0315x over previous
#include <cuda_runtime.h>
#include <cuda_bf16.h>
#include <cuda_fp16.h>
#include <cstdint>
#include <cstddef>

#define Bq   2
#define Sq   2048
#define HIDD 2048
#define NH   32
#define NKV  8
#define HD   64
#define QKVW ((NH + 2 * NKV) * HD)   /* 3072 */
#define GROUP (NH / NKV)             /* 4 */
#define SCALE 0.125f
#define LOG2E 1.4426950408889634f
#define QSCALE (SCALE * LOG2E)

#define MROWS   (Bq * Sq)            /* 4096 */
#define N_HID   (NH * HD)            /* 2048 */

// ---------------------------------------------------------------------------
// Scratch (device globals)
// ---------------------------------------------------------------------------
__device__ float g_qkv [(size_t)Bq * Sq * QKVW];

// fp16 operands for the two projections
__device__ __half g_hid_hi [(size_t)MROWS * HIDD];
__device__ __half g_hid_lo [(size_t)MROWS * HIDD];
__device__ __half g_wqkvT  [(size_t)QKVW * HIDD];    // [N, K] single fp16
__device__ __half g_woT    [(size_t)HIDD * N_HID];
__device__ __half g_attn_hi[(size_t)MROWS * N_HID];
__device__ __half g_attn_lo[(size_t)MROWS * N_HID];

// K bf16 hi/lo: [b, hk, kv, d]; V^T bf16 hi/lo: [b, hk, d, kv]
__device__ __nv_bfloat16 g_k_hi [(size_t)Bq * NKV * Sq * HD];
__device__ __nv_bfloat16 g_k_lo [(size_t)Bq * NKV * Sq * HD];
__device__ __nv_bfloat16 g_vt_hi[(size_t)Bq * NKV * HD * Sq];
__device__ __nv_bfloat16 g_vt_lo[(size_t)Bq * NKV * HD * Sq];

// ---------------------------------------------------------------------------
// Helpers
// ---------------------------------------------------------------------------
__device__ __forceinline__ uint32_t smem_u32(const void* p) {
    uint32_t a;
    asm("{ .reg .u64 t; cvta.to.shared.u64 t, %1; cvt.u32.u64 %0, t; }"
        : "=r"(a) : "l"(p));
    return a;
}
__device__ __forceinline__ uint32_t packbf(float x, float y) {   // lo=x, hi=y
    uint32_t r;
    asm("cvt.rn.bf16x2.f32 %0, %1, %2;" : "=r"(r) : "f"(y), "f"(x));
    return r;
}
__device__ __forceinline__ float2 unpackbf(uint32_t v) {
    __nv_bfloat162 t = *reinterpret_cast<__nv_bfloat162*>(&v);
    return make_float2(__bfloat162float(t.x), __bfloat162float(t.y));
}
__device__ __forceinline__ uint32_t packh(float x, float y) {    // lo=x, hi=y
    uint32_t r;
    asm("cvt.rn.f16x2.f32 %0, %1, %2;" : "=r"(r) : "f"(y), "f"(x));
    return r;
}
__device__ __forceinline__ float2 unpackh(uint32_t v) {
    __half2 t = *reinterpret_cast<__half2*>(&v);
    return make_float2(__half2float(t.x), __half2float(t.y));
}
__device__ __forceinline__ float ex2(float x) {
    float r; asm("ex2.approx.f32 %0, %1;" : "=f"(r) : "f"(x)); return r;
}

#define MMA_BF16(c, a, br0, br1) \
    asm volatile("mma.sync.aligned.m16n8k16.row.col.f32.bf16.bf16.f32 " \
        "{%0,%1,%2,%3}, {%4,%5,%6,%7}, {%8,%9}, {%0,%1,%2,%3};" \
        : "+f"((c)[0]), "+f"((c)[1]), "+f"((c)[2]), "+f"((c)[3]) \
        : "r"((a)[0]), "r"((a)[1]), "r"((a)[2]), "r"((a)[3]), "r"(br0), "r"(br1))

#define MMA_F16(c, a, br0, br1) \
    asm volatile("mma.sync.aligned.m16n8k16.row.col.f32.f16.f16.f32 " \
        "{%0,%1,%2,%3}, {%4,%5,%6,%7}, {%8,%9}, {%0,%1,%2,%3};" \
        : "+f"((c)[0]), "+f"((c)[1]), "+f"((c)[2]), "+f"((c)[3]) \
        : "r"((a)[0]), "r"((a)[1]), "r"((a)[2]), "r"((a)[3]), "r"(br0), "r"(br1))

#define LDMATRIX_X4(r, addr) \
    asm volatile("ldmatrix.sync.aligned.m8n8.x4.shared.b16 {%0,%1,%2,%3}, [%4];" \
        : "=r"((r)[0]), "=r"((r)[1]), "=r"((r)[2]), "=r"((r)[3]) : "r"(addr))

#define CP_ASYNC16(saddr, gptr) \
    asm volatile("cp.async.cg.shared.global [%0], [%1], 16;" :: "r"(saddr), "l"(gptr))
#define CP_COMMIT() asm volatile("cp.async.commit_group;" ::: "memory")
template <int N> __device__ __forceinline__ void cp_wait() {
    asm volatile("cp.async.wait_group %0;" :: "n"(N) : "memory");
}

// ---------------------------------------------------------------------------
// fp32 -> fp16 hi/lo split
// ---------------------------------------------------------------------------
__global__ void convert_split_h(const float* __restrict__ x,
                                __half* __restrict__ hi,
                                __half* __restrict__ lo, int n4)
{
    int i = blockIdx.x * blockDim.x + threadIdx.x;
    if (i >= n4) return;
    float4 v = ((const float4*)x)[i];
    uint32_t h01 = packh(v.x, v.y), h23 = packh(v.z, v.w);
    float2 f01 = unpackh(h01), f23 = unpackh(h23);
    uint32_t l01 = packh(v.x - f01.x, v.y - f01.y);
    uint32_t l23 = packh(v.z - f23.x, v.w - f23.y);
    ((uint2*)hi)[i] = make_uint2(h01, h23);
    ((uint2*)lo)[i] = make_uint2(l01, l23);
}

// ---------------------------------------------------------------------------
// Transpose fp32 B[R x C] -> fp16 [C x R]
// ---------------------------------------------------------------------------
__global__ void transpose_h(const float* __restrict__ B,
                            __half* __restrict__ T, int R, int C)
{
    __shared__ float t[32][33];
    int x = blockIdx.x * 32 + threadIdx.x;
    int y = blockIdx.y * 32 + threadIdx.y;
    #pragma unroll
    for (int j = 0; j < 32; j += 8)
        t[threadIdx.y + j][threadIdx.x] = B[(size_t)(y + j) * C + x];
    __syncthreads();
    int ox = blockIdx.y * 32 + threadIdx.x;
    int oy = blockIdx.x * 32 + threadIdx.y;
    #pragma unroll
    for (int j = 0; j < 32; j += 8)
        T[(size_t)(oy + j) * R + ox] = __float2half_rn(t[threadIdx.x][threadIdx.y + j]);
}

// ---------------------------------------------------------------------------
// GEMM: C[M,N] = (Ahi+Alo)[M,K] * B^T (B stored [N,K] fp16), 2-product fp16.
// CTA 128x128, 8 warps (warp 32x64), K-chunk 32, 2-stage cp.async pipeline,
// 2 CTAs/SM (R5-proven structure).
// ---------------------------------------------------------------------------
#define ROWB       80            /* 64B data + 16B pad */
#define TILEB      (128 * ROWB)  /* 10240 */
#define STAGEB     (3 * TILEB)   /* 30720: Ahi, Alo, B */
#define GEMM_SMEM  (2 * STAGEB)  /* 61440 */

__global__ __launch_bounds__(256, 2) void gemm_h(
    int M, int N, int K,
    const __half* __restrict__ Ahi, const __half* __restrict__ Alo,
    const __half* __restrict__ B,
    float* __restrict__ C)
{
    extern __shared__ char smem[];
    const uint32_t sbase = smem_u32(smem);
    const int tid  = threadIdx.x;
    const int wid  = tid >> 5;
    const int lane = tid & 31;
    const int m0 = blockIdx.y * 128;
    const int n0 = blockIdx.x * 128;
    const int wm = (wid >> 1) * 32;
    const int wn = (wid & 1) * 64;

    const __half* srcs[3] = {
        Ahi + (size_t)m0 * K, Alo + (size_t)m0 * K, B + (size_t)n0 * K
    };

    const int q  = lane >> 3;
    const int ri = lane & 7;
    const int a_row_add = ((q & 1) << 3) + ri;
    const int a_col_add = (q >> 1) << 3;
    const int b_row_add = ((q >> 1) << 3) + ri;
    const int b_col_add = (q & 1) << 3;

    float acc[2][8][4];
    #pragma unroll
    for (int mi = 0; mi < 2; mi++)
        #pragma unroll
        for (int ni = 0; ni < 8; ni++)
            #pragma unroll
            for (int c = 0; c < 4; c++) acc[mi][ni][c] = 0.f;

    const int NC = K >> 5;

    auto load_chunk = [&](int stage, int k0) {
        uint32_t sdst = sbase + stage * STAGEB;
        #pragma unroll
        for (int t = 0; t < 3; t++) {
            #pragma unroll
            for (int u = 0; u < 2; u++) {
                int idx = tid + u * 256;
                int row = idx >> 2;
                int seg = idx & 3;
                const __half* g = srcs[t] + (size_t)row * K + k0 + seg * 8;
                CP_ASYNC16(sdst + t * TILEB + row * ROWB + seg * 16, g);
            }
        }
        CP_COMMIT();
    };

    load_chunk(0, 0);

    for (int i = 0; i < NC; i++) {
        const int s = i & 1;
        if (i + 1 < NC) { load_chunk(s ^ 1, (i + 1) << 5); cp_wait<1>(); }
        else           { cp_wait<0>(); }
        __syncthreads();

        const uint32_t st = sbase + s * STAGEB;
        #pragma unroll
        for (int kk = 0; kk < 32; kk += 16) {
            uint32_t a_hi[2][4], a_lo[2][4];
            #pragma unroll
            for (int mi = 0; mi < 2; mi++) {
                int row = wm + mi * 16 + a_row_add;
                int col = kk + a_col_add;
                LDMATRIX_X4(a_hi[mi], st + 0 * TILEB + row * ROWB + col * 2);
                LDMATRIX_X4(a_lo[mi], st + 1 * TILEB + row * ROWB + col * 2);
            }
            #pragma unroll
            for (int nj = 0; nj < 4; nj++) {
                uint32_t bf[4];
                int row = wn + nj * 16 + b_row_add;
                int col = kk + b_col_add;
                LDMATRIX_X4(bf, st + 2 * TILEB + row * ROWB + col * 2);
                #pragma unroll
                for (int mi = 0; mi < 2; mi++) {
                    #pragma unroll
                    for (int hh = 0; hh < 2; hh++) {
                        int ni = nj * 2 + hh;
                        MMA_F16(acc[mi][ni], a_hi[mi], bf[hh*2], bf[hh*2+1]);
                        MMA_F16(acc[mi][ni], a_lo[mi], bf[hh*2], bf[hh*2+1]);
                    }
                }
            }
        }
        __syncthreads();
    }

    const int g  = lane >> 2;
    const int tg = lane & 3;
    #pragma unroll
    for (int mi = 0; mi < 2; mi++) {
        #pragma unroll
        for (int ni = 0; ni < 8; ni++) {
            int row = m0 + wm + mi * 16 + g;
            int col = n0 + wn + ni * 8 + tg * 2;
            *(float2*)(C + (size_t)row * N + col)       = make_float2(acc[mi][ni][0], acc[mi][ni][1]);
            *(float2*)(C + (size_t)(row + 8) * N + col) = make_float2(acc[mi][ni][2], acc[mi][ni][3]);
        }
    }
}

// ---------------------------------------------------------------------------
// RoPE
// ---------------------------------------------------------------------------
__global__ void rope_kernel(const int* __restrict__ positions)
{
    const int total = Bq * Sq * (NH + NKV) * (HD / 2);
    int idx = blockIdx.x * blockDim.x + threadIdx.x;
    if (idx >= total) return;

    int i  = idx & (HD / 2 - 1);
    int hh = (idx >> 5) % (NH + NKV);
    int bs = idx / ((HD / 2) * (NH + NKV));

    float pos = (float)positions[bs];
    float inv = __expf(-((float)(2 * i) / (float)HD) * 9.210340371976184f);
    float f = pos * inv;
    float c = cosf(f), s = sinf(f);

    float* p = g_qkv + (size_t)bs * QKVW + hh * HD;
    float x1 = p[i];
    float x2 = p[i + HD / 2];
    p[i]          = x1 * c - x2 * s;
    p[i + HD / 2] = x2 * c + x1 * s;
}

// ---------------------------------------------------------------------------
// K/V global bf16 hi/lo conversion; V transposed. grid (32, NKV, Bq), 256 thr
// ---------------------------------------------------------------------------
__global__ __launch_bounds__(256) void convert_kv()
{
    int jt = blockIdx.x, hk = blockIdx.y, b = blockIdx.z;
    int tid = threadIdx.x;
    __shared__ float vt[64][65];

    int r    = tid >> 2;
    int dseg = (tid & 3) * 16;

    const float* ksrc = g_qkv + (size_t)(b * Sq + jt * 64 + r) * QKVW + NH * HD + hk * HD;
    const float* vsrc = g_qkv + (size_t)(b * Sq + jt * 64 + r) * QKVW + (NH + NKV) * HD + hk * HD;
    __nv_bfloat16* khid = g_k_hi + ((size_t)(b * NKV + hk) * Sq + jt * 64 + r) * HD;
    __nv_bfloat16* klod = g_k_lo + ((size_t)(b * NKV + hk) * Sq + jt * 64 + r) * HD;

    #pragma unroll
    for (int i = 0; i < 4; i++) {
        int d = dseg + i * 4;
        float4 f = *(const float4*)(ksrc + d);
        uint32_t h01 = packbf(f.x, f.y), h23 = packbf(f.z, f.w);
        float2 u01 = unpackbf(h01), u23 = unpackbf(h23);
        uint32_t l01 = packbf(f.x - u01.x, f.y - u01.y);
        uint32_t l23 = packbf(f.z - u23.x, f.w - u23.y);
        *(uint2*)(khid + d) = make_uint2(h01, h23);
        *(uint2*)(klod + d) = make_uint2(l01, l23);

        float4 v = *(const float4*)(vsrc + d);
        vt[r][d + 0] = v.x; vt[r][d + 1] = v.y; vt[r][d + 2] = v.z; vt[r][d + 3] = v.w;
    }
    __syncthreads();

    int d = tid >> 2;
    int kseg = (tid & 3) * 16;
    uint32_t hi8[8], lo8[8];
    #pragma unroll
    for (int i = 0; i < 8; i++) {
        float a = vt[kseg + 2 * i][d];
        float c = vt[kseg + 2 * i + 1][d];
        uint32_t h = packbf(a, c);
        float2 u = unpackbf(h);
        hi8[i] = h;
        lo8[i] = packbf(a - u.x, c - u.y);
    }
    size_t vo = ((size_t)(b * NKV + hk) * HD + d) * Sq + jt * 64 + kseg;
    *(uint4*)(g_vt_hi + vo)     = make_uint4(hi8[0], hi8[1], hi8[2], hi8[3]);
    *(uint4*)(g_vt_hi + vo + 8) = make_uint4(hi8[4], hi8[5], hi8[6], hi8[7]);
    *(uint4*)(g_vt_lo + vo)     = make_uint4(lo8[0], lo8[1], lo8[2], lo8[3]);
    *(uint4*)(g_vt_lo + vo + 8) = make_uint4(lo8[4], lo8[5], lo8[6], lo8[7]);
}

// ---------------------------------------------------------------------------
// mma.sync flash attention (R5-proven). grid (16, NH, Bq), 256 threads.
// q-tile 128, kv-chunk 128 per stage. Epilogue writes fp16 hi/lo.
// ---------------------------------------------------------------------------
#define ATT_KROWB  144
#define ATT_KTILE  (128 * ATT_KROWB)
#define ATT_VROWB  272
#define ATT_VTILE  (64 * ATT_VROWB)
#define ATT_VOFF   (2 * ATT_KTILE)
#define ATT_STAGEB (ATT_VOFF + 2 * ATT_VTILE)
#define ATT_SMEM   (2 * ATT_STAGEB)

__global__ __launch_bounds__(256, 1) void attn_mma()
{
    const int qt = (int)gridDim.x - 1 - (int)blockIdx.x;
    const int h  = blockIdx.y;
    const int b  = blockIdx.z;
    const int hk = h / GROUP;
    const int q0 = qt * 128;

    extern __shared__ char smem[];
    const uint32_t sb = smem_u32(smem);
    const int tid  = threadIdx.x;
    const int wid  = tid >> 5;
    const int lane = tid & 31;
    const int wm   = wid * 16;
    const int g  = lane >> 2;
    const int tg = lane & 3;
    const int q  = lane >> 3;
    const int ri = lane & 7;
    const int b_row_add = ((q >> 1) << 3) + ri;
    const int b_col_add = (q & 1) << 3;

    uint32_t qa_hi[4][4], qa_lo[4][4];
    {
        const float* qbase = g_qkv + (size_t)(b * Sq + q0 + wm) * QKVW + h * HD;
        #pragma unroll
        for (int kb = 0; kb < 4; kb++) {
            #pragma unroll
            for (int p = 0; p < 4; p++) {
                int row = g + (p & 1) * 8;
                int col = kb * 16 + tg * 2 + (p >> 1) * 8;
                float2 f = *(const float2*)(qbase + (size_t)row * QKVW + col);
                f.x *= QSCALE; f.y *= QSCALE;
                uint32_t hh = packbf(f.x, f.y);
                float2 u = unpackbf(hh);
                qa_hi[kb][p] = hh;
                qa_lo[kb][p] = packbf(f.x - u.x, f.y - u.y);
            }
        }
    }

    float oacc[8][4];
    #pragma unroll
    for (int n = 0; n < 8; n++)
        #pragma unroll
        for (int j = 0; j < 4; j++) oacc[n][j] = 0.f;
    float m0 = -1e30f, m1 = -1e30f, l0 = 0.f, l1 = 0.f;

    const __nv_bfloat16* khi = g_k_hi  + (size_t)(b * NKV + hk) * Sq * HD;
    const __nv_bfloat16* klo = g_k_lo  + (size_t)(b * NKV + hk) * Sq * HD;
    const __nv_bfloat16* vhi = g_vt_hi + (size_t)(b * NKV + hk) * HD * Sq;
    const __nv_bfloat16* vlo = g_vt_lo + (size_t)(b * NKV + hk) * HD * Sq;

    const int nchunks = qt + 1;

    auto load = [&](int stg, int ct) {
        uint32_t dst = sb + stg * ATT_STAGEB;
        int j0 = ct * 128;
        #pragma unroll
        for (int k = 0; k < 16; k++) {
            int c = tid + k * 256;
            int t = c >> 10;
            if (t < 2) {
                int row = (c >> 3) & 127;
                int seg = c & 7;
                const __nv_bfloat16* src = (t == 0 ? khi : klo) + (size_t)(j0 + row) * HD + seg * 8;
                CP_ASYNC16(dst + t * ATT_KTILE + row * ATT_KROWB + seg * 16, src);
            } else {
                int row = (c >> 4) & 63;
                int seg = c & 15;
                const __nv_bfloat16* src = (t == 2 ? vhi : vlo) + (size_t)row * Sq + j0 + seg * 8;
                CP_ASYNC16(dst + ATT_VOFF + (t - 2) * ATT_VTILE + row * ATT_VROWB + seg * 16, src);
            }
        }
        CP_COMMIT();
    };

    load(0, 0);

    for (int t = 0; t < nchunks; t++) {
        const int s = t & 1;
        if (t + 1 < nchunks) { load(s ^ 1, t + 1); cp_wait<1>(); }
        else                 { cp_wait<0>(); }
        __syncthreads();

        const uint32_t st = sb + s * ATT_STAGEB;
        #pragma unroll
        for (int half = 0; half < 2; half++) {
            const int j0 = t * 128 + half * 64;
            if (j0 <= q0 + wm + 15) {
                float sc[8][4];
                #pragma unroll
                for (int n = 0; n < 8; n++)
                    #pragma unroll
                    for (int j = 0; j < 4; j++) sc[n][j] = 0.f;

                #pragma unroll
                for (int kb = 0; kb < 4; kb++) {
                    #pragma unroll
                    for (int nj = 0; nj < 4; nj++) {
                        uint32_t bh[4], bl[4];
                        uint32_t addr = st + (half * 64 + nj * 16 + b_row_add) * ATT_KROWB
                                        + (kb * 16 + b_col_add) * 2;
                        LDMATRIX_X4(bh, addr);
                        LDMATRIX_X4(bl, addr + ATT_KTILE);
                        #pragma unroll
                        for (int hh = 0; hh < 2; hh++) {
                            int n = nj * 2 + hh;
                            MMA_BF16(sc[n], qa_hi[kb], bh[hh*2], bh[hh*2+1]);
                            MMA_BF16(sc[n], qa_hi[kb], bl[hh*2], bl[hh*2+1]);
                            MMA_BF16(sc[n], qa_lo[kb], bh[hh*2], bh[hh*2+1]);
                        }
                    }
                }

                if (j0 + 63 > q0 + wm) {
                    int r0 = q0 + wm + g;
                    #pragma unroll
                    for (int n = 0; n < 8; n++) {
                        int cb = j0 + n * 8 + tg * 2;
                        if (cb     > r0)     sc[n][0] = -1e30f;
                        if (cb + 1 > r0)     sc[n][1] = -1e30f;
                        if (cb     > r0 + 8) sc[n][2] = -1e30f;
                        if (cb + 1 > r0 + 8) sc[n][3] = -1e30f;
                    }
                }

                float mx0 = -1e30f, mx1 = -1e30f;
                #pragma unroll
                for (int n = 0; n < 8; n++) {
                    mx0 = fmaxf(mx0, fmaxf(sc[n][0], sc[n][1]));
                    mx1 = fmaxf(mx1, fmaxf(sc[n][2], sc[n][3]));
                }
                mx0 = fmaxf(mx0, __shfl_xor_sync(0xffffffffu, mx0, 1));
                mx0 = fmaxf(mx0, __shfl_xor_sync(0xffffffffu, mx0, 2));
                mx1 = fmaxf(mx1, __shfl_xor_sync(0xffffffffu, mx1, 1));
                mx1 = fmaxf(mx1, __shfl_xor_sync(0xffffffffu, mx1, 2));

                float nm0 = fmaxf(m0, mx0), nm1 = fmaxf(m1, mx1);
                float corr0 = ex2(m0 - nm0), corr1 = ex2(m1 - nm1);
                m0 = nm0; m1 = nm1;

                float s0 = 0.f, s1 = 0.f;
                #pragma unroll
                for (int n = 0; n < 8; n++) {
                    sc[n][0] = ex2(sc[n][0] - nm0);
                    sc[n][1] = ex2(sc[n][1] - nm0);
                    sc[n][2] = ex2(sc[n][2] - nm1);
                    sc[n][3] = ex2(sc[n][3] - nm1);
                    s0 += sc[n][0] + sc[n][1];
                    s1 += sc[n][2] + sc[n][3];
                }
                s0 += __shfl_xor_sync(0xffffffffu, s0, 1);
                s0 += __shfl_xor_sync(0xffffffffu, s0, 2);
                s1 += __shfl_xor_sync(0xffffffffu, s1, 1);
                s1 += __shfl_xor_sync(0xffffffffu, s1, 2);
                l0 = l0 * corr0 + s0;
                l1 = l1 * corr1 + s1;

                #pragma unroll
                for (int n = 0; n < 8; n++) {
                    oacc[n][0] *= corr0; oacc[n][1] *= corr0;
                    oacc[n][2] *= corr1; oacc[n][3] *= corr1;
                }

                uint32_t pa_hi[4][4], pa_lo[4][4];
                #pragma unroll
                for (int kb = 0; kb < 4; kb++) {
                    #pragma unroll
                    for (int hh = 0; hh < 2; hh++) {
                        int n = 2 * kb + hh;
                        uint32_t h0 = packbf(sc[n][0], sc[n][1]);
                        uint32_t h1 = packbf(sc[n][2], sc[n][3]);
                        float2 u0 = unpackbf(h0), u1 = unpackbf(h1);
                        pa_hi[kb][hh * 2 + 0] = h0;
                        pa_hi[kb][hh * 2 + 1] = h1;
                        pa_lo[kb][hh * 2 + 0] = packbf(sc[n][0] - u0.x, sc[n][1] - u0.y);
                        pa_lo[kb][hh * 2 + 1] = packbf(sc[n][2] - u1.x, sc[n][3] - u1.y);
                    }
                }

                #pragma unroll
                for (int kb = 0; kb < 4; kb++) {
                    #pragma unroll
                    for (int dg = 0; dg < 4; dg++) {
                        uint32_t vh[4], vl[4];
                        uint32_t addr = st + ATT_VOFF + (dg * 16 + b_row_add) * ATT_VROWB
                                        + (half * 64 + kb * 16 + b_col_add) * 2;
                        LDMATRIX_X4(vh, addr);
                        LDMATRIX_X4(vl, addr + ATT_VTILE);
                        #pragma unroll
                        for (int hh = 0; hh < 2; hh++) {
                            int n = dg * 2 + hh;
                            MMA_BF16(oacc[n], pa_hi[kb], vh[hh*2], vh[hh*2+1]);
                            MMA_BF16(oacc[n], pa_hi[kb], vl[hh*2], vl[hh*2+1]);
                            MMA_BF16(oacc[n], pa_lo[kb], vh[hh*2], vh[hh*2+1]);
                        }
                    }
                }
            }
        }
        __syncthreads();
    }

    // ---- epilogue: normalize, fp16 hi/lo split ----
    float inv0 = 1.f / l0, inv1 = 1.f / l1;
    int row0 = q0 + wm + g;
    #pragma unroll
    for (int n = 0; n < 8; n++) {
        int col = h * HD + n * 8 + tg * 2;
        size_t o0 = (size_t)(b * Sq + row0) * N_HID + col;
        size_t o1 = (size_t)(b * Sq + row0 + 8) * N_HID + col;
        float a0 = oacc[n][0] * inv0, a1 = oacc[n][1] * inv0;
        float a2 = oacc[n][2] * inv1, a3 = oacc[n][3] * inv1;
        uint32_t h0 = packh(a0, a1), h1 = packh(a2, a3);
        float2 u0 = unpackh(h0), u1 = unpackh(h1);
        *(uint32_t*)(g_attn_hi + o0) = h0;
        *(uint32_t*)(g_attn_hi + o1) = h1;
        *(uint32_t*)(g_attn_lo + o0) = packh(a0 - u0.x, a1 - u0.y);
        *(uint32_t*)(g_attn_lo + o1) = packh(a2 - u1.x, a3 - u1.y);
    }
}

// ---------------------------------------------------------------------------
// Launch pipeline
// ---------------------------------------------------------------------------
extern "C" void kernel_launch(void* const* d_in, const int* in_sizes, int n_in,
                              void* d_out, int out_size)
{
    const int*   positions = (const int*)d_in[0];
    const float* hidden    = (const float*)d_in[1];
    const float* Wqkv      = (const float*)d_in[2];
    const float* Wo        = (const float*)d_in[3];
    float*       out       = (float*)d_out;

    float* qkv;
    cudaGetSymbolAddress((void**)&qkv, g_qkv);
    __half *hid_hi, *hid_lo, *wqkvT, *woT, *attn_hi, *attn_lo;
    cudaGetSymbolAddress((void**)&hid_hi,  g_hid_hi);
    cudaGetSymbolAddress((void**)&hid_lo,  g_hid_lo);
    cudaGetSymbolAddress((void**)&wqkvT,   g_wqkvT);
    cudaGetSymbolAddress((void**)&woT,     g_woT);
    cudaGetSymbolAddress((void**)&attn_hi, g_attn_hi);
    cudaGetSymbolAddress((void**)&attn_lo, g_attn_lo);

    cudaFuncSetAttribute(gemm_h,   cudaFuncAttributeMaxDynamicSharedMemorySize, GEMM_SMEM);
    cudaFuncSetAttribute(attn_mma, cudaFuncAttributeMaxDynamicSharedMemorySize, ATT_SMEM);

    // hidden -> fp16 hi/lo
    {
        int n4 = (MROWS * HIDD) / 4;
        convert_split_h<<<(n4 + 255) / 256, 256>>>(hidden, hid_hi, hid_lo, n4);
    }
    // Wqkv -> transposed fp16
    transpose_h<<<dim3(QKVW / 32, HIDD / 32), dim3(32, 8)>>>(Wqkv, wqkvT, HIDD, QKVW);

    // QKV projection (fp16 2-product)
    gemm_h<<<dim3(QKVW / 128, MROWS / 128), 256, GEMM_SMEM>>>(
        MROWS, QKVW, HIDD, hid_hi, hid_lo, wqkvT, qkv);

    // RoPE (q + k)
    {
        int total = Bq * Sq * (NH + NKV) * (HD / 2);
        rope_kernel<<<(total + 255) / 256, 256>>>(positions);
    }

    // K/V -> bf16 hi/lo (V transposed)
    convert_kv<<<dim3(Sq / 64, NKV, Bq), 256>>>();

    // Flash attention (writes fp16 hi/lo attn output)
    attn_mma<<<dim3(Sq / 128, NH, Bq), 256, ATT_SMEM>>>();

    // Wo -> transposed fp16
    transpose_h<<<dim3(HIDD / 32, N_HID / 32), dim3(32, 8)>>>(Wo, woT, N_HID, HIDD);

    // Output projection (fp16 2-product)
    gemm_h<<<dim3(HIDD / 128, MROWS / 128), 256, GEMM_SMEM>>>(
        MROWS, HIDD, N_HID, attn_hi, attn_lo, woT, out);
}

// round 9
// speedup vs baseline: 3.3895x; 1.1181x over previous
#include <cuda_runtime.h>
#include <cuda_bf16.h>
#include <cuda_fp16.h>
#include <cstdint>
#include <cstddef>

#define Bq   2
#define Sq   2048
#define HIDD 2048
#define NH   32
#define NKV  8
#define HD   64
#define QKVW ((NH + 2 * NKV) * HD)   /* 3072 */
#define GROUP (NH / NKV)             /* 4 */
#define SCALE 0.125f
#define LOG2E 1.4426950408889634f
#define QSCALE (SCALE * LOG2E)
#define ROPE_C 0.28782313662425575f  /* ln(10000)/32 */

#define MROWS   (Bq * Sq)            /* 4096 */
#define N_HID   (NH * HD)            /* 2048 */

// ---------------------------------------------------------------------------
// Scratch (device globals)
// ---------------------------------------------------------------------------
__device__ float g_qkv [(size_t)Bq * Sq * QKVW];

// fp16 operands for the two projections
__device__ __half g_hid_hi [(size_t)MROWS * HIDD];
__device__ __half g_hid_lo [(size_t)MROWS * HIDD];
__device__ __half g_wqkvT  [(size_t)QKVW * HIDD];
__device__ __half g_woT    [(size_t)HIDD * N_HID];
__device__ __half g_attn_hi[(size_t)MROWS * N_HID];
__device__ __half g_attn_lo[(size_t)MROWS * N_HID];

// K bf16 hi/lo (RoPE'd): [b, hk, kv, d]; V^T single fp16: [b, hk, d, kv]
__device__ __nv_bfloat16 g_k_hi [(size_t)Bq * NKV * Sq * HD];
__device__ __nv_bfloat16 g_k_lo [(size_t)Bq * NKV * Sq * HD];
__device__ __half        g_vt   [(size_t)Bq * NKV * HD * Sq];

// ---------------------------------------------------------------------------
// Helpers
// ---------------------------------------------------------------------------
__device__ __forceinline__ uint32_t smem_u32(const void* p) {
    uint32_t a;
    asm("{ .reg .u64 t; cvta.to.shared.u64 t, %1; cvt.u32.u64 %0, t; }"
        : "=r"(a) : "l"(p));
    return a;
}
__device__ __forceinline__ uint32_t packbf(float x, float y) {   // lo=x, hi=y
    uint32_t r;
    asm("cvt.rn.bf16x2.f32 %0, %1, %2;" : "=r"(r) : "f"(y), "f"(x));
    return r;
}
__device__ __forceinline__ float2 unpackbf(uint32_t v) {
    __nv_bfloat162 t = *reinterpret_cast<__nv_bfloat162*>(&v);
    return make_float2(__bfloat162float(t.x), __bfloat162float(t.y));
}
__device__ __forceinline__ uint32_t packh(float x, float y) {    // lo=x, hi=y
    uint32_t r;
    asm("cvt.rn.f16x2.f32 %0, %1, %2;" : "=r"(r) : "f"(y), "f"(x));
    return r;
}
__device__ __forceinline__ float2 unpackh(uint32_t v) {
    __half2 t = *reinterpret_cast<__half2*>(&v);
    return make_float2(__half2float(t.x), __half2float(t.y));
}
__device__ __forceinline__ float ex2(float x) {
    float r; asm("ex2.approx.f32 %0, %1;" : "=f"(r) : "f"(x)); return r;
}

#define MMA_BF16(c, a, br0, br1) \
    asm volatile("mma.sync.aligned.m16n8k16.row.col.f32.bf16.bf16.f32 " \
        "{%0,%1,%2,%3}, {%4,%5,%6,%7}, {%8,%9}, {%0,%1,%2,%3};" \
        : "+f"((c)[0]), "+f"((c)[1]), "+f"((c)[2]), "+f"((c)[3]) \
        : "r"((a)[0]), "r"((a)[1]), "r"((a)[2]), "r"((a)[3]), "r"(br0), "r"(br1))

#define MMA_F16(c, a, br0, br1) \
    asm volatile("mma.sync.aligned.m16n8k16.row.col.f32.f16.f16.f32 " \
        "{%0,%1,%2,%3}, {%4,%5,%6,%7}, {%8,%9}, {%0,%1,%2,%3};" \
        : "+f"((c)[0]), "+f"((c)[1]), "+f"((c)[2]), "+f"((c)[3]) \
        : "r"((a)[0]), "r"((a)[1]), "r"((a)[2]), "r"((a)[3]), "r"(br0), "r"(br1))

#define LDMATRIX_X4(r, addr) \
    asm volatile("ldmatrix.sync.aligned.m8n8.x4.shared.b16 {%0,%1,%2,%3}, [%4];" \
        : "=r"((r)[0]), "=r"((r)[1]), "=r"((r)[2]), "=r"((r)[3]) : "r"(addr))

#define CP_ASYNC16(saddr, gptr) \
    asm volatile("cp.async.cg.shared.global [%0], [%1], 16;" :: "r"(saddr), "l"(gptr))
#define CP_COMMIT() asm volatile("cp.async.commit_group;" ::: "memory")
template <int N> __device__ __forceinline__ void cp_wait() {
    asm volatile("cp.async.wait_group %0;" :: "n"(N) : "memory");
}

// ---------------------------------------------------------------------------
// fp32 -> fp16 hi/lo split
// ---------------------------------------------------------------------------
__global__ void convert_split_h(const float* __restrict__ x,
                                __half* __restrict__ hi,
                                __half* __restrict__ lo, int n4)
{
    int i = blockIdx.x * blockDim.x + threadIdx.x;
    if (i >= n4) return;
    float4 v = ((const float4*)x)[i];
    uint32_t h01 = packh(v.x, v.y), h23 = packh(v.z, v.w);
    float2 f01 = unpackh(h01), f23 = unpackh(h23);
    uint32_t l01 = packh(v.x - f01.x, v.y - f01.y);
    uint32_t l23 = packh(v.z - f23.x, v.w - f23.y);
    ((uint2*)hi)[i] = make_uint2(h01, h23);
    ((uint2*)lo)[i] = make_uint2(l01, l23);
}

// ---------------------------------------------------------------------------
// Transpose fp32 B[R x C] -> fp16 [C x R]
// ---------------------------------------------------------------------------
__global__ void transpose_h(const float* __restrict__ B,
                            __half* __restrict__ T, int R, int C)
{
    __shared__ float t[32][33];
    int x = blockIdx.x * 32 + threadIdx.x;
    int y = blockIdx.y * 32 + threadIdx.y;
    #pragma unroll
    for (int j = 0; j < 32; j += 8)
        t[threadIdx.y + j][threadIdx.x] = B[(size_t)(y + j) * C + x];
    __syncthreads();
    int ox = blockIdx.y * 32 + threadIdx.x;
    int oy = blockIdx.x * 32 + threadIdx.y;
    #pragma unroll
    for (int j = 0; j < 32; j += 8)
        T[(size_t)(oy + j) * R + ox] = __float2half_rn(t[threadIdx.x][threadIdx.y + j]);
}

// ---------------------------------------------------------------------------
// GEMM: C[M,N] = (Ahi+Alo)[M,K] * B^T (fp16 2-product).
// CTA 128x128, 8 warps, K-chunk 64 (half the syncs), 2-stage, 2 CTAs/SM.
// ---------------------------------------------------------------------------
#define ROWB       144           /* 128B data + 16B pad */
#define TILEB      (128 * ROWB)  /* 18432 */
#define STAGEB     (3 * TILEB)   /* 55296: Ahi, Alo, B */
#define GEMM_SMEM  (2 * STAGEB)  /* 110592 */

__global__ __launch_bounds__(256, 2) void gemm_h(
    int M, int N, int K,
    const __half* __restrict__ Ahi, const __half* __restrict__ Alo,
    const __half* __restrict__ B,
    float* __restrict__ C)
{
    extern __shared__ char smem[];
    const uint32_t sbase = smem_u32(smem);
    const int tid  = threadIdx.x;
    const int wid  = tid >> 5;
    const int lane = tid & 31;
    const int m0 = blockIdx.y * 128;
    const int n0 = blockIdx.x * 128;
    const int wm = (wid >> 1) * 32;
    const int wn = (wid & 1) * 64;

    const __half* srcs[3] = {
        Ahi + (size_t)m0 * K, Alo + (size_t)m0 * K, B + (size_t)n0 * K
    };

    const int q  = lane >> 3;
    const int ri = lane & 7;
    const int a_row_add = ((q & 1) << 3) + ri;
    const int a_col_add = (q >> 1) << 3;
    const int b_row_add = ((q >> 1) << 3) + ri;
    const int b_col_add = (q & 1) << 3;

    float acc[2][8][4];
    #pragma unroll
    for (int mi = 0; mi < 2; mi++)
        #pragma unroll
        for (int ni = 0; ni < 8; ni++)
            #pragma unroll
            for (int c = 0; c < 4; c++) acc[mi][ni][c] = 0.f;

    const int NC = K >> 6;   // chunks of 64

    auto load_chunk = [&](int stage, int k0) {
        uint32_t sdst = sbase + stage * STAGEB;
        #pragma unroll
        for (int t = 0; t < 3; t++) {
            #pragma unroll
            for (int u = 0; u < 4; u++) {
                int idx = tid + u * 256;      // 0..1023
                int row = idx >> 3;
                int seg = idx & 7;
                const __half* g = srcs[t] + (size_t)row * K + k0 + seg * 8;
                CP_ASYNC16(sdst + t * TILEB + row * ROWB + seg * 16, g);
            }
        }
        CP_COMMIT();
    };

    load_chunk(0, 0);

    for (int i = 0; i < NC; i++) {
        const int s = i & 1;
        if (i + 1 < NC) { load_chunk(s ^ 1, (i + 1) << 6); cp_wait<1>(); }
        else           { cp_wait<0>(); }
        __syncthreads();

        const uint32_t st = sbase + s * STAGEB;
        #pragma unroll
        for (int kk = 0; kk < 64; kk += 16) {
            uint32_t a_hi[2][4], a_lo[2][4];
            #pragma unroll
            for (int mi = 0; mi < 2; mi++) {
                int row = wm + mi * 16 + a_row_add;
                int col = kk + a_col_add;
                LDMATRIX_X4(a_hi[mi], st + 0 * TILEB + row * ROWB + col * 2);
                LDMATRIX_X4(a_lo[mi], st + 1 * TILEB + row * ROWB + col * 2);
            }
            #pragma unroll
            for (int nj = 0; nj < 4; nj++) {
                uint32_t bf[4];
                int row = wn + nj * 16 + b_row_add;
                int col = kk + b_col_add;
                LDMATRIX_X4(bf, st + 2 * TILEB + row * ROWB + col * 2);
                #pragma unroll
                for (int mi = 0; mi < 2; mi++) {
                    #pragma unroll
                    for (int hh = 0; hh < 2; hh++) {
                        int ni = nj * 2 + hh;
                        MMA_F16(acc[mi][ni], a_hi[mi], bf[hh*2], bf[hh*2+1]);
                        MMA_F16(acc[mi][ni], a_lo[mi], bf[hh*2], bf[hh*2+1]);
                    }
                }
            }
        }
        __syncthreads();
    }

    const int g  = lane >> 2;
    const int tg = lane & 3;
    #pragma unroll
    for (int mi = 0; mi < 2; mi++) {
        #pragma unroll
        for (int ni = 0; ni < 8; ni++) {
            int row = m0 + wm + mi * 16 + g;
            int col = n0 + wn + ni * 8 + tg * 2;
            *(float2*)(C + (size_t)row * N + col)       = make_float2(acc[mi][ni][0], acc[mi][ni][1]);
            *(float2*)(C + (size_t)(row + 8) * N + col) = make_float2(acc[mi][ni][2], acc[mi][ni][3]);
        }
    }
}

// ---------------------------------------------------------------------------
// K/V conversion with fused RoPE on K. grid (32, NKV, Bq), 256 threads.
// K -> bf16 hi/lo (RoPE'd); V -> transposed single fp16.
// ---------------------------------------------------------------------------
__global__ __launch_bounds__(256) void convert_kv(const int* __restrict__ positions)
{
    int jt = blockIdx.x, hk = blockIdx.y, b = blockIdx.z;
    int tid = threadIdx.x;
    __shared__ float vt[64][65];

    int r  = tid >> 2;            // 0..63 (kv row within tile)
    int q4 = tid & 3;             // col quarter

    const float* ksrc = g_qkv + (size_t)(b * Sq + jt * 64 + r) * QKVW + NH * HD + hk * HD;
    const float* vsrc = g_qkv + (size_t)(b * Sq + jt * 64 + r) * QKVW + (NH + NKV) * HD + hk * HD;
    __nv_bfloat16* khid = g_k_hi + ((size_t)(b * NKV + hk) * Sq + jt * 64 + r) * HD;
    __nv_bfloat16* klod = g_k_lo + ((size_t)(b * NKV + hk) * Sq + jt * 64 + r) * HD;

    float pos = (float)positions[b * Sq + jt * 64 + r];

    // ---- K path: cols [q4*8, q4*8+8) and partners +32, RoPE fused ----
    #pragma unroll
    for (int i = 0; i < 2; i++) {
        int d = q4 * 8 + i * 4;
        float4 x1 = *(const float4*)(ksrc + d);
        float4 x2 = *(const float4*)(ksrc + d + 32);
        float o1[4], o2[4];
        float xa[4] = {x1.x, x1.y, x1.z, x1.w};
        float xb[4] = {x2.x, x2.y, x2.z, x2.w};
        #pragma unroll
        for (int j = 0; j < 4; j++) {
            float sn, cs;
            sincosf(pos * __expf(-(float)(d + j) * ROPE_C), &sn, &cs);
            o1[j] = xa[j] * cs - xb[j] * sn;
            o2[j] = xb[j] * cs + xa[j] * sn;
        }
        // write bf16 hi/lo for cols d..d+3 and d+32..d+35
        uint32_t h01 = packbf(o1[0], o1[1]), h23 = packbf(o1[2], o1[3]);
        float2 u01 = unpackbf(h01), u23 = unpackbf(h23);
        *(uint2*)(khid + d) = make_uint2(h01, h23);
        *(uint2*)(klod + d) = make_uint2(packbf(o1[0]-u01.x, o1[1]-u01.y),
                                         packbf(o1[2]-u23.x, o1[3]-u23.y));
        uint32_t g01 = packbf(o2[0], o2[1]), g23 = packbf(o2[2], o2[3]);
        float2 w01 = unpackbf(g01), w23 = unpackbf(g23);
        *(uint2*)(khid + d + 32) = make_uint2(g01, g23);
        *(uint2*)(klod + d + 32) = make_uint2(packbf(o2[0]-w01.x, o2[1]-w01.y),
                                              packbf(o2[2]-w23.x, o2[3]-w23.y));
    }

    // ---- V path: stage fp32 into smem ----
    int dseg = (tid & 3) * 16;
    #pragma unroll
    for (int i = 0; i < 4; i++) {
        int d = dseg + i * 4;
        float4 v = *(const float4*)(vsrc + d);
        vt[r][d + 0] = v.x; vt[r][d + 1] = v.y; vt[r][d + 2] = v.z; vt[r][d + 3] = v.w;
    }
    __syncthreads();

    // transposed single-fp16 write
    int d = tid >> 2;
    int kseg = (tid & 3) * 16;
    uint32_t h8[8];
    #pragma unroll
    for (int i = 0; i < 8; i++)
        h8[i] = packh(vt[kseg + 2 * i][d], vt[kseg + 2 * i + 1][d]);
    __half* vdst = g_vt + ((size_t)(b * NKV + hk) * HD + d) * Sq + jt * 64 + kseg;
    *(uint4*)(vdst)     = make_uint4(h8[0], h8[1], h8[2], h8[3]);
    *(uint4*)(vdst + 8) = make_uint4(h8[4], h8[5], h8[6], h8[7]);
}

// ---------------------------------------------------------------------------
// mma.sync flash attention with fused Q-RoPE. grid (16, NH, Bq), 256 threads.
// QK^T: bf16 3-product. PV: fp16 2-product (P hi/lo, V single).
// ---------------------------------------------------------------------------
#define ATT_KROWB  144
#define ATT_KTILE  (128 * ATT_KROWB)          /* 18432 */
#define ATT_VROWB  272
#define ATT_VTILE  (64 * ATT_VROWB)           /* 17408 */
#define ATT_VOFF   (2 * ATT_KTILE)            /* 36864 */
#define ATT_STAGEB (ATT_VOFF + ATT_VTILE)     /* 54272 */
#define ATT_SMEM   (2 * ATT_STAGEB)           /* 108544 */

__global__ __launch_bounds__(256, 1) void attn_mma(const int* __restrict__ positions)
{
    const int qt = (int)gridDim.x - 1 - (int)blockIdx.x;
    const int h  = blockIdx.y;
    const int b  = blockIdx.z;
    const int hk = h / GROUP;
    const int q0 = qt * 128;

    extern __shared__ char smem[];
    const uint32_t sb = smem_u32(smem);
    const int tid  = threadIdx.x;
    const int wid  = tid >> 5;
    const int lane = tid & 31;
    const int wm   = wid * 16;
    const int g  = lane >> 2;
    const int tg = lane & 3;
    const int q  = lane >> 3;
    const int ri = lane & 7;
    const int b_row_add = ((q >> 1) << 3) + ri;
    const int b_col_add = (q & 1) << 3;

    // ---- Q fragments: load, RoPE, scale, bf16 hi/lo split ----
    uint32_t qa_hi[4][4], qa_lo[4][4];
    {
        const float* qbase = g_qkv + (size_t)(b * Sq + q0 + wm) * QKVW + h * HD;
        float2 f[4][4];
        #pragma unroll
        for (int kb = 0; kb < 4; kb++) {
            #pragma unroll
            for (int p = 0; p < 4; p++) {
                int row = g + (p & 1) * 8;
                int col = kb * 16 + tg * 2 + (p >> 1) * 8;
                f[kb][p] = *(const float2*)(qbase + (size_t)row * QKVW + col);
            }
        }
        float pos0 = (float)positions[b * Sq + q0 + wm + g];
        float pos1 = (float)positions[b * Sq + q0 + wm + g + 8];
        #pragma unroll
        for (int kb = 0; kb < 2; kb++) {
            #pragma unroll
            for (int p = 0; p < 4; p++) {
                int c0 = kb * 16 + tg * 2 + ((p >> 1) << 3);
                float pos = (p & 1) ? pos1 : pos0;
                float s0, c0v, s1, c1v;
                sincosf(pos * __expf(-(float)c0 * ROPE_C), &s0, &c0v);
                sincosf(pos * __expf(-(float)(c0 + 1) * ROPE_C), &s1, &c1v);
                float2 x1 = f[kb][p], x2 = f[kb + 2][p];
                f[kb][p]     = make_float2(x1.x * c0v - x2.x * s0, x1.y * c1v - x2.y * s1);
                f[kb + 2][p] = make_float2(x2.x * c0v + x1.x * s0, x2.y * c1v + x1.y * s1);
            }
        }
        #pragma unroll
        for (int kb = 0; kb < 4; kb++) {
            #pragma unroll
            for (int p = 0; p < 4; p++) {
                float fx = f[kb][p].x * QSCALE;
                float fy = f[kb][p].y * QSCALE;
                uint32_t hh = packbf(fx, fy);
                float2 u = unpackbf(hh);
                qa_hi[kb][p] = hh;
                qa_lo[kb][p] = packbf(fx - u.x, fy - u.y);
            }
        }
    }

    float oacc[8][4];
    #pragma unroll
    for (int n = 0; n < 8; n++)
        #pragma unroll
        for (int j = 0; j < 4; j++) oacc[n][j] = 0.f;
    float m0 = -1e30f, m1 = -1e30f, l0 = 0.f, l1 = 0.f;

    const __nv_bfloat16* khi = g_k_hi + (size_t)(b * NKV + hk) * Sq * HD;
    const __nv_bfloat16* klo = g_k_lo + (size_t)(b * NKV + hk) * Sq * HD;
    const __half*        vts = g_vt   + (size_t)(b * NKV + hk) * HD * Sq;

    const int nchunks = qt + 1;

    auto load = [&](int stg, int ct) {
        uint32_t dst = sb + stg * ATT_STAGEB;
        int j0 = ct * 128;
        #pragma unroll
        for (int k = 0; k < 12; k++) {
            int c = tid + k * 256;    // 0..3071
            if (c < 2048) {
                int t = c >> 10;
                int row = (c >> 3) & 127;
                int seg = c & 7;
                const __nv_bfloat16* src = (t == 0 ? khi : klo) + (size_t)(j0 + row) * HD + seg * 8;
                CP_ASYNC16(dst + t * ATT_KTILE + row * ATT_KROWB + seg * 16, src);
            } else {
                int cv = c - 2048;
                int row = cv >> 4;
                int seg = cv & 15;
                const __half* src = vts + (size_t)row * Sq + j0 + seg * 8;
                CP_ASYNC16(dst + ATT_VOFF + row * ATT_VROWB + seg * 16, src);
            }
        }
        CP_COMMIT();
    };

    load(0, 0);

    for (int t = 0; t < nchunks; t++) {
        const int s = t & 1;
        if (t + 1 < nchunks) { load(s ^ 1, t + 1); cp_wait<1>(); }
        else                 { cp_wait<0>(); }
        __syncthreads();

        const uint32_t st = sb + s * ATT_STAGEB;
        #pragma unroll
        for (int half = 0; half < 2; half++) {
            const int j0 = t * 128 + half * 64;
            if (j0 <= q0 + wm + 15) {
                // ---- S = Q @ K^T (bf16 3-product) ----
                float sc[8][4];
                #pragma unroll
                for (int n = 0; n < 8; n++)
                    #pragma unroll
                    for (int j = 0; j < 4; j++) sc[n][j] = 0.f;

                #pragma unroll
                for (int kb = 0; kb < 4; kb++) {
                    #pragma unroll
                    for (int nj = 0; nj < 4; nj++) {
                        uint32_t bh[4], bl[4];
                        uint32_t addr = st + (half * 64 + nj * 16 + b_row_add) * ATT_KROWB
                                        + (kb * 16 + b_col_add) * 2;
                        LDMATRIX_X4(bh, addr);
                        LDMATRIX_X4(bl, addr + ATT_KTILE);
                        #pragma unroll
                        for (int hh = 0; hh < 2; hh++) {
                            int n = nj * 2 + hh;
                            MMA_BF16(sc[n], qa_hi[kb], bh[hh*2], bh[hh*2+1]);
                            MMA_BF16(sc[n], qa_hi[kb], bl[hh*2], bl[hh*2+1]);
                            MMA_BF16(sc[n], qa_lo[kb], bh[hh*2], bh[hh*2+1]);
                        }
                    }
                }

                // ---- causal mask (diagonal tiles) ----
                if (j0 + 63 > q0 + wm) {
                    int r0 = q0 + wm + g;
                    #pragma unroll
                    for (int n = 0; n < 8; n++) {
                        int cb = j0 + n * 8 + tg * 2;
                        if (cb     > r0)     sc[n][0] = -1e30f;
                        if (cb + 1 > r0)     sc[n][1] = -1e30f;
                        if (cb     > r0 + 8) sc[n][2] = -1e30f;
                        if (cb + 1 > r0 + 8) sc[n][3] = -1e30f;
                    }
                }

                // ---- online softmax ----
                float mx0 = -1e30f, mx1 = -1e30f;
                #pragma unroll
                for (int n = 0; n < 8; n++) {
                    mx0 = fmaxf(mx0, fmaxf(sc[n][0], sc[n][1]));
                    mx1 = fmaxf(mx1, fmaxf(sc[n][2], sc[n][3]));
                }
                mx0 = fmaxf(mx0, __shfl_xor_sync(0xffffffffu, mx0, 1));
                mx0 = fmaxf(mx0, __shfl_xor_sync(0xffffffffu, mx0, 2));
                mx1 = fmaxf(mx1, __shfl_xor_sync(0xffffffffu, mx1, 1));
                mx1 = fmaxf(mx1, __shfl_xor_sync(0xffffffffu, mx1, 2));

                float nm0 = fmaxf(m0, mx0), nm1 = fmaxf(m1, mx1);
                float corr0 = ex2(m0 - nm0), corr1 = ex2(m1 - nm1);
                m0 = nm0; m1 = nm1;

                float s0 = 0.f, s1 = 0.f;
                #pragma unroll
                for (int n = 0; n < 8; n++) {
                    sc[n][0] = ex2(sc[n][0] - nm0);
                    sc[n][1] = ex2(sc[n][1] - nm0);
                    sc[n][2] = ex2(sc[n][2] - nm1);
                    sc[n][3] = ex2(sc[n][3] - nm1);
                    s0 += sc[n][0] + sc[n][1];
                    s1 += sc[n][2] + sc[n][3];
                }
                s0 += __shfl_xor_sync(0xffffffffu, s0, 1);
                s0 += __shfl_xor_sync(0xffffffffu, s0, 2);
                s1 += __shfl_xor_sync(0xffffffffu, s1, 1);
                s1 += __shfl_xor_sync(0xffffffffu, s1, 2);
                l0 = l0 * corr0 + s0;
                l1 = l1 * corr1 + s1;

                #pragma unroll
                for (int n = 0; n < 8; n++) {
                    oacc[n][0] *= corr0; oacc[n][1] *= corr0;
                    oacc[n][2] *= corr1; oacc[n][3] *= corr1;
                }

                // ---- pack P (fp16 hi/lo) as a-frags ----
                uint32_t pa_hi[4][4], pa_lo[4][4];
                #pragma unroll
                for (int kb = 0; kb < 4; kb++) {
                    #pragma unroll
                    for (int hh = 0; hh < 2; hh++) {
                        int n = 2 * kb + hh;
                        uint32_t h0 = packh(sc[n][0], sc[n][1]);
                        uint32_t h1 = packh(sc[n][2], sc[n][3]);
                        float2 u0 = unpackh(h0), u1 = unpackh(h1);
                        pa_hi[kb][hh * 2 + 0] = h0;
                        pa_hi[kb][hh * 2 + 1] = h1;
                        pa_lo[kb][hh * 2 + 0] = packh(sc[n][0] - u0.x, sc[n][1] - u0.y);
                        pa_lo[kb][hh * 2 + 1] = packh(sc[n][2] - u1.x, sc[n][3] - u1.y);
                    }
                }

                // ---- O += P @ V (fp16 2-product, V single) ----
                #pragma unroll
                for (int kb = 0; kb < 4; kb++) {
                    #pragma unroll
                    for (int dg = 0; dg < 4; dg++) {
                        uint32_t vh[4];
                        uint32_t addr = st + ATT_VOFF + (dg * 16 + b_row_add) * ATT_VROWB
                                        + (half * 64 + kb * 16 + b_col_add) * 2;
                        LDMATRIX_X4(vh, addr);
                        #pragma unroll
                        for (int hh = 0; hh < 2; hh++) {
                            int n = dg * 2 + hh;
                            MMA_F16(oacc[n], pa_hi[kb], vh[hh*2], vh[hh*2+1]);
                            MMA_F16(oacc[n], pa_lo[kb], vh[hh*2], vh[hh*2+1]);
                        }
                    }
                }
            }
        }
        __syncthreads();
    }

    // ---- epilogue: normalize, fp16 hi/lo split ----
    float inv0 = 1.f / l0, inv1 = 1.f / l1;
    int row0 = q0 + wm + g;
    #pragma unroll
    for (int n = 0; n < 8; n++) {
        int col = h * HD + n * 8 + tg * 2;
        size_t o0 = (size_t)(b * Sq + row0) * N_HID + col;
        size_t o1 = (size_t)(b * Sq + row0 + 8) * N_HID + col;
        float a0 = oacc[n][0] * inv0, a1 = oacc[n][1] * inv0;
        float a2 = oacc[n][2] * inv1, a3 = oacc[n][3] * inv1;
        uint32_t h0 = packh(a0, a1), h1 = packh(a2, a3);
        float2 u0 = unpackh(h0), u1 = unpackh(h1);
        *(uint32_t*)(g_attn_hi + o0) = h0;
        *(uint32_t*)(g_attn_hi + o1) = h1;
        *(uint32_t*)(g_attn_lo + o0) = packh(a0 - u0.x, a1 - u0.y);
        *(uint32_t*)(g_attn_lo + o1) = packh(a2 - u1.x, a3 - u1.y);
    }
}

// ---------------------------------------------------------------------------
// Launch pipeline
// ---------------------------------------------------------------------------
extern "C" void kernel_launch(void* const* d_in, const int* in_sizes, int n_in,
                              void* d_out, int out_size)
{
    const int*   positions = (const int*)d_in[0];
    const float* hidden    = (const float*)d_in[1];
    const float* Wqkv      = (const float*)d_in[2];
    const float* Wo        = (const float*)d_in[3];
    float*       out       = (float*)d_out;

    float* qkv;
    cudaGetSymbolAddress((void**)&qkv, g_qkv);
    __half *hid_hi, *hid_lo, *wqkvT, *woT, *attn_hi, *attn_lo;
    cudaGetSymbolAddress((void**)&hid_hi,  g_hid_hi);
    cudaGetSymbolAddress((void**)&hid_lo,  g_hid_lo);
    cudaGetSymbolAddress((void**)&wqkvT,   g_wqkvT);
    cudaGetSymbolAddress((void**)&woT,     g_woT);
    cudaGetSymbolAddress((void**)&attn_hi, g_attn_hi);
    cudaGetSymbolAddress((void**)&attn_lo, g_attn_lo);

    cudaFuncSetAttribute(gemm_h,   cudaFuncAttributeMaxDynamicSharedMemorySize, GEMM_SMEM);
    cudaFuncSetAttribute(attn_mma, cudaFuncAttributeMaxDynamicSharedMemorySize, ATT_SMEM);

    // hidden -> fp16 hi/lo
    {
        int n4 = (MROWS * HIDD) / 4;
        convert_split_h<<<(n4 + 255) / 256, 256>>>(hidden, hid_hi, hid_lo, n4);
    }
    // Wqkv -> transposed fp16
    transpose_h<<<dim3(QKVW / 32, HIDD / 32), dim3(32, 8)>>>(Wqkv, wqkvT, HIDD, QKVW);

    // QKV projection (fp16 2-product, K-chunk 64)
    gemm_h<<<dim3(QKVW / 128, MROWS / 128), 256, GEMM_SMEM>>>(
        MROWS, QKVW, HIDD, hid_hi, hid_lo, wqkvT, qkv);

    // K/V convert (RoPE fused into K path)
    convert_kv<<<dim3(Sq / 64, NKV, Bq), 256>>>(positions);

    // Flash attention (RoPE fused into Q load; writes fp16 hi/lo)
    attn_mma<<<dim3(Sq / 128, NH, Bq), 256, ATT_SMEM>>>(positions);

    // Wo -> transposed fp16
    transpose_h<<<dim3(HIDD / 32, N_HID / 32), dim3(32, 8)>>>(Wo, woT, N_HID, HIDD);

    // Output projection (fp16 2-product, K-chunk 64)
    gemm_h<<<dim3(HIDD / 128, MROWS / 128), 256, GEMM_SMEM>>>(
        MROWS, HIDD, N_HID, attn_hi, attn_lo, woT, out);
}

// round 10
// speedup vs baseline: 3.4397x; 1.0148x over previous
#include <cuda_runtime.h>
#include <cuda_bf16.h>
#include <cuda_fp16.h>
#include <cstdint>
#include <cstddef>

#define Bq   2
#define Sq   2048
#define HIDD 2048
#define NH   32
#define NKV  8
#define HD   64
#define QKVW ((NH + 2 * NKV) * HD)   /* 3072 */
#define GROUP (NH / NKV)             /* 4 */
#define SCALE 0.125f
#define LOG2E 1.4426950408889634f
#define QSCALE (SCALE * LOG2E)
#define ROPE_C 0.28782313662425575f  /* ln(10000)/32 */

#define MROWS   (Bq * Sq)            /* 4096 */
#define N_HID   (NH * HD)            /* 2048 */

// ---------------------------------------------------------------------------
// Scratch (device globals)
// ---------------------------------------------------------------------------
__device__ float g_qkv [(size_t)Bq * Sq * QKVW];

__device__ __half g_hid_hi [(size_t)MROWS * HIDD];
__device__ __half g_hid_lo [(size_t)MROWS * HIDD];
__device__ __half g_wqkvT  [(size_t)QKVW * HIDD];
__device__ __half g_woT    [(size_t)HIDD * N_HID];
__device__ __half g_attn_hi[(size_t)MROWS * N_HID];
__device__ __half g_attn_lo[(size_t)MROWS * N_HID];

__device__ __nv_bfloat16 g_k_hi [(size_t)Bq * NKV * Sq * HD];
__device__ __nv_bfloat16 g_k_lo [(size_t)Bq * NKV * Sq * HD];
__device__ __half        g_vt   [(size_t)Bq * NKV * HD * Sq];

// ---------------------------------------------------------------------------
// Helpers
// ---------------------------------------------------------------------------
__device__ __forceinline__ uint32_t smem_u32(const void* p) {
    uint32_t a;
    asm("{ .reg .u64 t; cvta.to.shared.u64 t, %1; cvt.u32.u64 %0, t; }"
        : "=r"(a) : "l"(p));
    return a;
}
__device__ __forceinline__ uint32_t packbf(float x, float y) {   // lo=x, hi=y
    uint32_t r;
    asm("cvt.rn.bf16x2.f32 %0, %1, %2;" : "=r"(r) : "f"(y), "f"(x));
    return r;
}
__device__ __forceinline__ float2 unpackbf(uint32_t v) {
    __nv_bfloat162 t = *reinterpret_cast<__nv_bfloat162*>(&v);
    return make_float2(__bfloat162float(t.x), __bfloat162float(t.y));
}
__device__ __forceinline__ uint32_t packh(float x, float y) {    // lo=x, hi=y
    uint32_t r;
    asm("cvt.rn.f16x2.f32 %0, %1, %2;" : "=r"(r) : "f"(y), "f"(x));
    return r;
}
__device__ __forceinline__ float2 unpackh(uint32_t v) {
    __half2 t = *reinterpret_cast<__half2*>(&v);
    return make_float2(__half2float(t.x), __half2float(t.y));
}
__device__ __forceinline__ float ex2(float x) {
    float r; asm("ex2.approx.f32 %0, %1;" : "=f"(r) : "f"(x)); return r;
}

#define MMA_BF16(c, a, br0, br1) \
    asm volatile("mma.sync.aligned.m16n8k16.row.col.f32.bf16.bf16.f32 " \
        "{%0,%1,%2,%3}, {%4,%5,%6,%7}, {%8,%9}, {%0,%1,%2,%3};" \
        : "+f"((c)[0]), "+f"((c)[1]), "+f"((c)[2]), "+f"((c)[3]) \
        : "r"((a)[0]), "r"((a)[1]), "r"((a)[2]), "r"((a)[3]), "r"(br0), "r"(br1))

#define MMA_F16(c, a, br0, br1) \
    asm volatile("mma.sync.aligned.m16n8k16.row.col.f32.f16.f16.f32 " \
        "{%0,%1,%2,%3}, {%4,%5,%6,%7}, {%8,%9}, {%0,%1,%2,%3};" \
        : "+f"((c)[0]), "+f"((c)[1]), "+f"((c)[2]), "+f"((c)[3]) \
        : "r"((a)[0]), "r"((a)[1]), "r"((a)[2]), "r"((a)[3]), "r"(br0), "r"(br1))

#define LDMATRIX_X4(r, addr) \
    asm volatile("ldmatrix.sync.aligned.m8n8.x4.shared.b16 {%0,%1,%2,%3}, [%4];" \
        : "=r"((r)[0]), "=r"((r)[1]), "=r"((r)[2]), "=r"((r)[3]) : "r"(addr))

#define CP_ASYNC16(saddr, gptr) \
    asm volatile("cp.async.cg.shared.global [%0], [%1], 16;" :: "r"(saddr), "l"(gptr))
#define CP_COMMIT() asm volatile("cp.async.commit_group;" ::: "memory")
template <int N> __device__ __forceinline__ void cp_wait() {
    asm volatile("cp.async.wait_group %0;" :: "n"(N) : "memory");
}

// ---------------------------------------------------------------------------
// fp32 -> fp16 hi/lo split
// ---------------------------------------------------------------------------
__global__ void convert_split_h(const float* __restrict__ x,
                                __half* __restrict__ hi,
                                __half* __restrict__ lo, int n4)
{
    int i = blockIdx.x * blockDim.x + threadIdx.x;
    if (i >= n4) return;
    float4 v = ((const float4*)x)[i];
    uint32_t h01 = packh(v.x, v.y), h23 = packh(v.z, v.w);
    float2 f01 = unpackh(h01), f23 = unpackh(h23);
    uint32_t l01 = packh(v.x - f01.x, v.y - f01.y);
    uint32_t l23 = packh(v.z - f23.x, v.w - f23.y);
    ((uint2*)hi)[i] = make_uint2(h01, h23);
    ((uint2*)lo)[i] = make_uint2(l01, l23);
}

// ---------------------------------------------------------------------------
// Transpose fp32 B[R x C] -> fp16 [C x R]
// ---------------------------------------------------------------------------
__global__ void transpose_h(const float* __restrict__ B,
                            __half* __restrict__ T, int R, int C)
{
    __shared__ float t[32][33];
    int x = blockIdx.x * 32 + threadIdx.x;
    int y = blockIdx.y * 32 + threadIdx.y;
    #pragma unroll
    for (int j = 0; j < 32; j += 8)
        t[threadIdx.y + j][threadIdx.x] = B[(size_t)(y + j) * C + x];
    __syncthreads();
    int ox = blockIdx.y * 32 + threadIdx.x;
    int oy = blockIdx.x * 32 + threadIdx.y;
    #pragma unroll
    for (int j = 0; j < 32; j += 8)
        T[(size_t)(oy + j) * R + ox] = __float2half_rn(t[threadIdx.x][threadIdx.y + j]);
}

// ---------------------------------------------------------------------------
// Persistent GEMM: C[M,N] = (Ahi+Alo)[M,K] * B^T (fp16 2-product).
// CTA tile 128x128, 8 warps, K-chunk 64, 2-stage, 2 CTAs/SM.
// Grid = min(296, ntiles); each CTA loops tiles to kill wave-quantization tail.
// ---------------------------------------------------------------------------
#define ROWB       144           /* 128B data + 16B pad */
#define TILEB      (128 * ROWB)  /* 18432 */
#define STAGEB     (3 * TILEB)   /* 55296 */
#define GEMM_SMEM  (2 * STAGEB)  /* 110592 */

__global__ __launch_bounds__(256, 2) void gemm_h(
    int M, int N, int K,
    const __half* __restrict__ Ahi, const __half* __restrict__ Alo,
    const __half* __restrict__ B,
    float* __restrict__ C)
{
    extern __shared__ char smem[];
    const uint32_t sbase = smem_u32(smem);
    const int tid  = threadIdx.x;
    const int wid  = tid >> 5;
    const int lane = tid & 31;
    const int wm = (wid >> 1) * 32;
    const int wn = (wid & 1) * 64;

    const int q  = lane >> 3;
    const int ri = lane & 7;
    const int a_row_add = ((q & 1) << 3) + ri;
    const int a_col_add = (q >> 1) << 3;
    const int b_row_add = ((q >> 1) << 3) + ri;
    const int b_col_add = (q & 1) << 3;
    const int go = lane >> 2;
    const int tg = lane & 3;

    const int nx = N >> 7;
    const int ntiles = (M >> 7) * nx;
    const int NC = K >> 6;

    for (int tile = blockIdx.x; tile < ntiles; tile += gridDim.x) {
        const int m0 = (tile / nx) * 128;
        const int n0 = (tile % nx) * 128;

        const __half* srcs[3] = {
            Ahi + (size_t)m0 * K, Alo + (size_t)m0 * K, B + (size_t)n0 * K
        };

        float acc[2][8][4];
        #pragma unroll
        for (int mi = 0; mi < 2; mi++)
            #pragma unroll
            for (int ni = 0; ni < 8; ni++)
                #pragma unroll
                for (int c = 0; c < 4; c++) acc[mi][ni][c] = 0.f;

        auto load_chunk = [&](int stage, int k0) {
            uint32_t sdst = sbase + stage * STAGEB;
            #pragma unroll
            for (int t = 0; t < 3; t++) {
                #pragma unroll
                for (int u = 0; u < 4; u++) {
                    int idx = tid + u * 256;
                    int row = idx >> 3;
                    int seg = idx & 7;
                    const __half* g = srcs[t] + (size_t)row * K + k0 + seg * 8;
                    CP_ASYNC16(sdst + t * TILEB + row * ROWB + seg * 16, g);
                }
            }
            CP_COMMIT();
        };

        __syncthreads();   // protect smem reuse across tiles
        load_chunk(0, 0);

        for (int i = 0; i < NC; i++) {
            const int s = i & 1;
            if (i + 1 < NC) { load_chunk(s ^ 1, (i + 1) << 6); cp_wait<1>(); }
            else           { cp_wait<0>(); }
            __syncthreads();

            const uint32_t st = sbase + s * STAGEB;
            #pragma unroll
            for (int kk = 0; kk < 64; kk += 16) {
                uint32_t a_hi[2][4], a_lo[2][4];
                #pragma unroll
                for (int mi = 0; mi < 2; mi++) {
                    int row = wm + mi * 16 + a_row_add;
                    int col = kk + a_col_add;
                    LDMATRIX_X4(a_hi[mi], st + 0 * TILEB + row * ROWB + col * 2);
                    LDMATRIX_X4(a_lo[mi], st + 1 * TILEB + row * ROWB + col * 2);
                }
                #pragma unroll
                for (int nj = 0; nj < 4; nj++) {
                    uint32_t bf[4];
                    int row = wn + nj * 16 + b_row_add;
                    int col = kk + b_col_add;
                    LDMATRIX_X4(bf, st + 2 * TILEB + row * ROWB + col * 2);
                    #pragma unroll
                    for (int mi = 0; mi < 2; mi++) {
                        #pragma unroll
                        for (int hh = 0; hh < 2; hh++) {
                            int ni = nj * 2 + hh;
                            MMA_F16(acc[mi][ni], a_hi[mi], bf[hh*2], bf[hh*2+1]);
                            MMA_F16(acc[mi][ni], a_lo[mi], bf[hh*2], bf[hh*2+1]);
                        }
                    }
                }
            }
            __syncthreads();
        }

        #pragma unroll
        for (int mi = 0; mi < 2; mi++) {
            #pragma unroll
            for (int ni = 0; ni < 8; ni++) {
                int row = m0 + wm + mi * 16 + go;
                int col = n0 + wn + ni * 8 + tg * 2;
                *(float2*)(C + (size_t)row * N + col)       = make_float2(acc[mi][ni][0], acc[mi][ni][1]);
                *(float2*)(C + (size_t)(row + 8) * N + col) = make_float2(acc[mi][ni][2], acc[mi][ni][3]);
            }
        }
    }
}

// ---------------------------------------------------------------------------
// K/V conversion with fused RoPE on K. grid (32, NKV, Bq), 256 threads.
// ---------------------------------------------------------------------------
__global__ __launch_bounds__(256) void convert_kv(const int* __restrict__ positions)
{
    int jt = blockIdx.x, hk = blockIdx.y, b = blockIdx.z;
    int tid = threadIdx.x;
    __shared__ float vt[64][65];

    int r  = tid >> 2;
    int q4 = tid & 3;

    const float* ksrc = g_qkv + (size_t)(b * Sq + jt * 64 + r) * QKVW + NH * HD + hk * HD;
    const float* vsrc = g_qkv + (size_t)(b * Sq + jt * 64 + r) * QKVW + (NH + NKV) * HD + hk * HD;
    __nv_bfloat16* khid = g_k_hi + ((size_t)(b * NKV + hk) * Sq + jt * 64 + r) * HD;
    __nv_bfloat16* klod = g_k_lo + ((size_t)(b * NKV + hk) * Sq + jt * 64 + r) * HD;

    float pos = (float)positions[b * Sq + jt * 64 + r];

    #pragma unroll
    for (int i = 0; i < 2; i++) {
        int d = q4 * 8 + i * 4;
        float4 x1 = *(const float4*)(ksrc + d);
        float4 x2 = *(const float4*)(ksrc + d + 32);
        float o1[4], o2[4];
        float xa[4] = {x1.x, x1.y, x1.z, x1.w};
        float xb[4] = {x2.x, x2.y, x2.z, x2.w};
        #pragma unroll
        for (int j = 0; j < 4; j++) {
            float sn, cs;
            sincosf(pos * __expf(-(float)(d + j) * ROPE_C), &sn, &cs);
            o1[j] = xa[j] * cs - xb[j] * sn;
            o2[j] = xb[j] * cs + xa[j] * sn;
        }
        uint32_t h01 = packbf(o1[0], o1[1]), h23 = packbf(o1[2], o1[3]);
        float2 u01 = unpackbf(h01), u23 = unpackbf(h23);
        *(uint2*)(khid + d) = make_uint2(h01, h23);
        *(uint2*)(klod + d) = make_uint2(packbf(o1[0]-u01.x, o1[1]-u01.y),
                                         packbf(o1[2]-u23.x, o1[3]-u23.y));
        uint32_t g01 = packbf(o2[0], o2[1]), g23 = packbf(o2[2], o2[3]);
        float2 w01 = unpackbf(g01), w23 = unpackbf(g23);
        *(uint2*)(khid + d + 32) = make_uint2(g01, g23);
        *(uint2*)(klod + d + 32) = make_uint2(packbf(o2[0]-w01.x, o2[1]-w01.y),
                                              packbf(o2[2]-w23.x, o2[3]-w23.y));
    }

    int dseg = (tid & 3) * 16;
    #pragma unroll
    for (int i = 0; i < 4; i++) {
        int d = dseg + i * 4;
        float4 v = *(const float4*)(vsrc + d);
        vt[r][d + 0] = v.x; vt[r][d + 1] = v.y; vt[r][d + 2] = v.z; vt[r][d + 3] = v.w;
    }
    __syncthreads();

    int d = tid >> 2;
    int kseg = (tid & 3) * 16;
    uint32_t h8[8];
    #pragma unroll
    for (int i = 0; i < 8; i++)
        h8[i] = packh(vt[kseg + 2 * i][d], vt[kseg + 2 * i + 1][d]);
    __half* vdst = g_vt + ((size_t)(b * NKV + hk) * HD + d) * Sq + jt * 64 + kseg;
    *(uint4*)(vdst)     = make_uint4(h8[0], h8[1], h8[2], h8[3]);
    *(uint4*)(vdst + 8) = make_uint4(h8[4], h8[5], h8[6], h8[7]);
}

// ---------------------------------------------------------------------------
// mma.sync flash attention with fused Q-RoPE (R9-proven).
// ---------------------------------------------------------------------------
#define ATT_KROWB  144
#define ATT_KTILE  (128 * ATT_KROWB)
#define ATT_VROWB  272
#define ATT_VTILE  (64 * ATT_VROWB)
#define ATT_VOFF   (2 * ATT_KTILE)
#define ATT_STAGEB (ATT_VOFF + ATT_VTILE)
#define ATT_SMEM   (2 * ATT_STAGEB)

__global__ __launch_bounds__(256, 1) void attn_mma(const int* __restrict__ positions)
{
    const int qt = (int)gridDim.x - 1 - (int)blockIdx.x;
    const int h  = blockIdx.y;
    const int b  = blockIdx.z;
    const int hk = h / GROUP;
    const int q0 = qt * 128;

    extern __shared__ char smem[];
    const uint32_t sb = smem_u32(smem);
    const int tid  = threadIdx.x;
    const int wid  = tid >> 5;
    const int lane = tid & 31;
    const int wm   = wid * 16;
    const int g  = lane >> 2;
    const int tg = lane & 3;
    const int q  = lane >> 3;
    const int ri = lane & 7;
    const int b_row_add = ((q >> 1) << 3) + ri;
    const int b_col_add = (q & 1) << 3;

    uint32_t qa_hi[4][4], qa_lo[4][4];
    {
        const float* qbase = g_qkv + (size_t)(b * Sq + q0 + wm) * QKVW + h * HD;
        float2 f[4][4];
        #pragma unroll
        for (int kb = 0; kb < 4; kb++) {
            #pragma unroll
            for (int p = 0; p < 4; p++) {
                int row = g + (p & 1) * 8;
                int col = kb * 16 + tg * 2 + (p >> 1) * 8;
                f[kb][p] = *(const float2*)(qbase + (size_t)row * QKVW + col);
            }
        }
        float pos0 = (float)positions[b * Sq + q0 + wm + g];
        float pos1 = (float)positions[b * Sq + q0 + wm + g + 8];
        #pragma unroll
        for (int kb = 0; kb < 2; kb++) {
            #pragma unroll
            for (int p = 0; p < 4; p++) {
                int c0 = kb * 16 + tg * 2 + ((p >> 1) << 3);
                float pos = (p & 1) ? pos1 : pos0;
                float s0, c0v, s1, c1v;
                sincosf(pos * __expf(-(float)c0 * ROPE_C), &s0, &c0v);
                sincosf(pos * __expf(-(float)(c0 + 1) * ROPE_C), &s1, &c1v);
                float2 x1 = f[kb][p], x2 = f[kb + 2][p];
                f[kb][p]     = make_float2(x1.x * c0v - x2.x * s0, x1.y * c1v - x2.y * s1);
                f[kb + 2][p] = make_float2(x2.x * c0v + x1.x * s0, x2.y * c1v + x1.y * s1);
            }
        }
        #pragma unroll
        for (int kb = 0; kb < 4; kb++) {
            #pragma unroll
            for (int p = 0; p < 4; p++) {
                float fx = f[kb][p].x * QSCALE;
                float fy = f[kb][p].y * QSCALE;
                uint32_t hh = packbf(fx, fy);
                float2 u = unpackbf(hh);
                qa_hi[kb][p] = hh;
                qa_lo[kb][p] = packbf(fx - u.x, fy - u.y);
            }
        }
    }

    float oacc[8][4];
    #pragma unroll
    for (int n = 0; n < 8; n++)
        #pragma unroll
        for (int j = 0; j < 4; j++) oacc[n][j] = 0.f;
    float m0 = -1e30f, m1 = -1e30f, l0 = 0.f, l1 = 0.f;

    const __nv_bfloat16* khi = g_k_hi + (size_t)(b * NKV + hk) * Sq * HD;
    const __nv_bfloat16* klo = g_k_lo + (size_t)(b * NKV + hk) * Sq * HD;
    const __half*        vts = g_vt   + (size_t)(b * NKV + hk) * HD * Sq;

    const int nchunks = qt + 1;

    auto load = [&](int stg, int ct) {
        uint32_t dst = sb + stg * ATT_STAGEB;
        int j0 = ct * 128;
        #pragma unroll
        for (int k = 0; k < 12; k++) {
            int c = tid + k * 256;
            if (c < 2048) {
                int t = c >> 10;
                int row = (c >> 3) & 127;
                int seg = c & 7;
                const __nv_bfloat16* src = (t == 0 ? khi : klo) + (size_t)(j0 + row) * HD + seg * 8;
                CP_ASYNC16(dst + t * ATT_KTILE + row * ATT_KROWB + seg * 16, src);
            } else {
                int cv = c - 2048;
                int row = cv >> 4;
                int seg = cv & 15;
                const __half* src = vts + (size_t)row * Sq + j0 + seg * 8;
                CP_ASYNC16(dst + ATT_VOFF + row * ATT_VROWB + seg * 16, src);
            }
        }
        CP_COMMIT();
    };

    load(0, 0);

    for (int t = 0; t < nchunks; t++) {
        const int s = t & 1;
        if (t + 1 < nchunks) { load(s ^ 1, t + 1); cp_wait<1>(); }
        else                 { cp_wait<0>(); }
        __syncthreads();

        const uint32_t st = sb + s * ATT_STAGEB;
        #pragma unroll
        for (int half = 0; half < 2; half++) {
            const int j0 = t * 128 + half * 64;
            if (j0 <= q0 + wm + 15) {
                float sc[8][4];
                #pragma unroll
                for (int n = 0; n < 8; n++)
                    #pragma unroll
                    for (int j = 0; j < 4; j++) sc[n][j] = 0.f;

                #pragma unroll
                for (int kb = 0; kb < 4; kb++) {
                    #pragma unroll
                    for (int nj = 0; nj < 4; nj++) {
                        uint32_t bh[4], bl[4];
                        uint32_t addr = st + (half * 64 + nj * 16 + b_row_add) * ATT_KROWB
                                        + (kb * 16 + b_col_add) * 2;
                        LDMATRIX_X4(bh, addr);
                        LDMATRIX_X4(bl, addr + ATT_KTILE);
                        #pragma unroll
                        for (int hh = 0; hh < 2; hh++) {
                            int n = nj * 2 + hh;
                            MMA_BF16(sc[n], qa_hi[kb], bh[hh*2], bh[hh*2+1]);
                            MMA_BF16(sc[n], qa_hi[kb], bl[hh*2], bl[hh*2+1]);
                            MMA_BF16(sc[n], qa_lo[kb], bh[hh*2], bh[hh*2+1]);
                        }
                    }
                }

                if (j0 + 63 > q0 + wm) {
                    int r0 = q0 + wm + g;
                    #pragma unroll
                    for (int n = 0; n < 8; n++) {
                        int cb = j0 + n * 8 + tg * 2;
                        if (cb     > r0)     sc[n][0] = -1e30f;
                        if (cb + 1 > r0)     sc[n][1] = -1e30f;
                        if (cb     > r0 + 8) sc[n][2] = -1e30f;
                        if (cb + 1 > r0 + 8) sc[n][3] = -1e30f;
                    }
                }

                float mx0 = -1e30f, mx1 = -1e30f;
                #pragma unroll
                for (int n = 0; n < 8; n++) {
                    mx0 = fmaxf(mx0, fmaxf(sc[n][0], sc[n][1]));
                    mx1 = fmaxf(mx1, fmaxf(sc[n][2], sc[n][3]));
                }
                mx0 = fmaxf(mx0, __shfl_xor_sync(0xffffffffu, mx0, 1));
                mx0 = fmaxf(mx0, __shfl_xor_sync(0xffffffffu, mx0, 2));
                mx1 = fmaxf(mx1, __shfl_xor_sync(0xffffffffu, mx1, 1));
                mx1 = fmaxf(mx1, __shfl_xor_sync(0xffffffffu, mx1, 2));

                float nm0 = fmaxf(m0, mx0), nm1 = fmaxf(m1, mx1);
                float corr0 = ex2(m0 - nm0), corr1 = ex2(m1 - nm1);
                m0 = nm0; m1 = nm1;

                float s0 = 0.f, s1 = 0.f;
                #pragma unroll
                for (int n = 0; n < 8; n++) {
                    sc[n][0] = ex2(sc[n][0] - nm0);
                    sc[n][1] = ex2(sc[n][1] - nm0);
                    sc[n][2] = ex2(sc[n][2] - nm1);
                    sc[n][3] = ex2(sc[n][3] - nm1);
                    s0 += sc[n][0] + sc[n][1];
                    s1 += sc[n][2] + sc[n][3];
                }
                s0 += __shfl_xor_sync(0xffffffffu, s0, 1);
                s0 += __shfl_xor_sync(0xffffffffu, s0, 2);
                s1 += __shfl_xor_sync(0xffffffffu, s1, 1);
                s1 += __shfl_xor_sync(0xffffffffu, s1, 2);
                l0 = l0 * corr0 + s0;
                l1 = l1 * corr1 + s1;

                #pragma unroll
                for (int n = 0; n < 8; n++) {
                    oacc[n][0] *= corr0; oacc[n][1] *= corr0;
                    oacc[n][2] *= corr1; oacc[n][3] *= corr1;
                }

                uint32_t pa_hi[4][4], pa_lo[4][4];
                #pragma unroll
                for (int kb = 0; kb < 4; kb++) {
                    #pragma unroll
                    for (int hh = 0; hh < 2; hh++) {
                        int n = 2 * kb + hh;
                        uint32_t h0 = packh(sc[n][0], sc[n][1]);
                        uint32_t h1 = packh(sc[n][2], sc[n][3]);
                        float2 u0 = unpackh(h0), u1 = unpackh(h1);
                        pa_hi[kb][hh * 2 + 0] = h0;
                        pa_hi[kb][hh * 2 + 1] = h1;
                        pa_lo[kb][hh * 2 + 0] = packh(sc[n][0] - u0.x, sc[n][1] - u0.y);
                        pa_lo[kb][hh * 2 + 1] = packh(sc[n][2] - u1.x, sc[n][3] - u1.y);
                    }
                }

                #pragma unroll
                for (int kb = 0; kb < 4; kb++) {
                    #pragma unroll
                    for (int dg = 0; dg < 4; dg++) {
                        uint32_t vh[4];
                        uint32_t addr = st + ATT_VOFF + (dg * 16 + b_row_add) * ATT_VROWB
                                        + (half * 64 + kb * 16 + b_col_add) * 2;
                        LDMATRIX_X4(vh, addr);
                        #pragma unroll
                        for (int hh = 0; hh < 2; hh++) {
                            int n = dg * 2 + hh;
                            MMA_F16(oacc[n], pa_hi[kb], vh[hh*2], vh[hh*2+1]);
                            MMA_F16(oacc[n], pa_lo[kb], vh[hh*2], vh[hh*2+1]);
                        }
                    }
                }
            }
        }
        __syncthreads();
    }

    float inv0 = 1.f / l0, inv1 = 1.f / l1;
    int row0 = q0 + wm + g;
    #pragma unroll
    for (int n = 0; n < 8; n++) {
        int col = h * HD + n * 8 + tg * 2;
        size_t o0 = (size_t)(b * Sq + row0) * N_HID + col;
        size_t o1 = (size_t)(b * Sq + row0 + 8) * N_HID + col;
        float a0 = oacc[n][0] * inv0, a1 = oacc[n][1] * inv0;
        float a2 = oacc[n][2] * inv1, a3 = oacc[n][3] * inv1;
        uint32_t h0 = packh(a0, a1), h1 = packh(a2, a3);
        float2 u0 = unpackh(h0), u1 = unpackh(h1);
        *(uint32_t*)(g_attn_hi + o0) = h0;
        *(uint32_t*)(g_attn_hi + o1) = h1;
        *(uint32_t*)(g_attn_lo + o0) = packh(a0 - u0.x, a1 - u0.y);
        *(uint32_t*)(g_attn_lo + o1) = packh(a2 - u1.x, a3 - u1.y);
    }
}

// ---------------------------------------------------------------------------
// Launch pipeline (stream-forked: weight transposes overlap the main chain)
// ---------------------------------------------------------------------------
extern "C" void kernel_launch(void* const* d_in, const int* in_sizes, int n_in,
                              void* d_out, int out_size)
{
    const int*   positions = (const int*)d_in[0];
    const float* hidden    = (const float*)d_in[1];
    const float* Wqkv      = (const float*)d_in[2];
    const float* Wo        = (const float*)d_in[3];
    float*       out       = (float*)d_out;

    float* qkv;
    cudaGetSymbolAddress((void**)&qkv, g_qkv);
    __half *hid_hi, *hid_lo, *wqkvT, *woT, *attn_hi, *attn_lo;
    cudaGetSymbolAddress((void**)&hid_hi,  g_hid_hi);
    cudaGetSymbolAddress((void**)&hid_lo,  g_hid_lo);
    cudaGetSymbolAddress((void**)&wqkvT,   g_wqkvT);
    cudaGetSymbolAddress((void**)&woT,     g_woT);
    cudaGetSymbolAddress((void**)&attn_hi, g_attn_hi);
    cudaGetSymbolAddress((void**)&attn_lo, g_attn_lo);

    cudaFuncSetAttribute(gemm_h,   cudaFuncAttributeMaxDynamicSharedMemorySize, GEMM_SMEM);
    cudaFuncSetAttribute(attn_mma, cudaFuncAttributeMaxDynamicSharedMemorySize, ATT_SMEM);

    // lazy-init side stream + events (resources only; same work every call)
    static cudaStream_t s2 = nullptr;
    static cudaEvent_t eFork = nullptr, eQkvW = nullptr, eWoW = nullptr;
    if (!s2) {
        cudaStreamCreateWithFlags(&s2, cudaStreamNonBlocking);
        cudaEventCreateWithFlags(&eFork, cudaEventDisableTiming);
        cudaEventCreateWithFlags(&eQkvW, cudaEventDisableTiming);
        cudaEventCreateWithFlags(&eWoW,  cudaEventDisableTiming);
    }

    const int GEMM_GRID = 296;   // 148 SMs x 2 CTAs

    // fork: side stream does both weight transposes
    cudaEventRecord(eFork, 0);
    cudaStreamWaitEvent(s2, eFork, 0);
    transpose_h<<<dim3(QKVW / 32, HIDD / 32), dim3(32, 8), 0, s2>>>(Wqkv, wqkvT, HIDD, QKVW);
    cudaEventRecord(eQkvW, s2);
    transpose_h<<<dim3(HIDD / 32, N_HID / 32), dim3(32, 8), 0, s2>>>(Wo, woT, N_HID, HIDD);
    cudaEventRecord(eWoW, s2);

    // main chain
    {
        int n4 = (MROWS * HIDD) / 4;
        convert_split_h<<<(n4 + 255) / 256, 256>>>(hidden, hid_hi, hid_lo, n4);
    }
    cudaStreamWaitEvent(0, eQkvW, 0);
    gemm_h<<<GEMM_GRID, 256, GEMM_SMEM>>>(
        MROWS, QKVW, HIDD, hid_hi, hid_lo, wqkvT, qkv);

    convert_kv<<<dim3(Sq / 64, NKV, Bq), 256>>>(positions);

    attn_mma<<<dim3(Sq / 128, NH, Bq), 256, ATT_SMEM>>>(positions);

    cudaStreamWaitEvent(0, eWoW, 0);
    gemm_h<<<GEMM_GRID, 256, GEMM_SMEM>>>(
        MROWS, HIDD, N_HID, attn_hi, attn_lo, woT, out);
}